// round 9
// baseline (speedup 1.0000x reference)
#include <cuda_runtime.h>
#include <cuda_bf16.h>
#include <math.h>

#define NN 100000
#define EE 1000000
#define NEG_SLOPE 0.2f

// ---------------- scratch (device globals; referenced directly by kernels) --
__device__ float g_h[(size_t)NN * 64];     // current layer feature h
__device__ float g_agg[(size_t)NN * 64];   // layer-1 aggregated output (+b1)
__device__ float g_as[NN];                 // alpha_src per node
__device__ float g_ad[NN];                 // alpha_dst per node
__device__ int   g_cnt[NN];                // histogram / scatter cursors
__device__ int   g_rowptr[NN + 1];         // CSR row pointers (by dst)
__device__ int   g_part[128];              // scan partials
__device__ int   g_esrc[EE];               // CSR: src node per edge slot
__device__ int   g_is64;                   // 1 if edge_index delivered as int64

// ---------------- dtype probe for edge_index --------------------------------
// If values are int64 (all < 2^31, nonnegative), every odd int32 word (the
// high half) is 0. If int32, odd positions hold random indices in [0,1e5),
// so the OR over 1024 of them is nonzero with overwhelming probability.
__global__ void detect_kernel(const int* __restrict__ ei32) {
    __shared__ int acc;
    int t = threadIdx.x;
    if (t == 0) acc = 0;
    __syncthreads();
    int v = 0;
    for (int i = t; i < 1024; i += 256) v |= ei32[2 * i + 1];
    if (v) atomicOr(&acc, 1);
    __syncthreads();
    if (t == 0) g_is64 = (acc == 0) ? 1 : 0;
}

__device__ __forceinline__ int edge_at(const int* ei32, long long idx) {
    if (g_is64) return (int)((const long long*)ei32)[idx];
    return ei32[idx];
}

// ---------------- CSR build kernels -----------------------------------------
__global__ void zero_cnt_kernel() {
    int i = blockIdx.x * blockDim.x + threadIdx.x;
    if (i < NN) g_cnt[i] = 0;
}

__global__ void hist_kernel(const int* __restrict__ ei32) {
    int i = blockIdx.x * blockDim.x + threadIdx.x;
    if (i >= EE) return;
    int d = edge_at(ei32, (long long)EE + i);
    if ((unsigned)d < NN) atomicAdd(&g_cnt[d], 1);
}

__global__ void scan1_kernel() {
    __shared__ int sm[1024];
    int t = threadIdx.x;
    int g = blockIdx.x * 1024 + t;
    int v = (g < NN) ? g_cnt[g] : 0;
    sm[t] = v;
    __syncthreads();
    for (int off = 1; off < 1024; off <<= 1) {
        int x = (t >= off) ? sm[t - off] : 0;
        __syncthreads();
        sm[t] += x;
        __syncthreads();
    }
    if (g < NN) g_rowptr[g] = sm[t] - v;   // exclusive
    if (t == 1023) g_part[blockIdx.x] = sm[t];
}

__global__ void scan2_kernel(int nb) {
    if (threadIdx.x == 0) {
        int acc = 0;
        for (int i = 0; i < nb; i++) { int v = g_part[i]; g_part[i] = acc; acc += v; }
    }
}

__global__ void scan3_kernel() {
    int g = blockIdx.x * blockDim.x + threadIdx.x;
    if (g < NN) g_rowptr[g] += g_part[g >> 10];
    if (g == 0) g_rowptr[NN] = EE;
}

__global__ void scatter_kernel(const int* __restrict__ ei32) {
    int i = blockIdx.x * blockDim.x + threadIdx.x;
    if (i >= EE) return;
    int s = edge_at(ei32, i);
    int d = edge_at(ei32, (long long)EE + i);
    if ((unsigned)s >= NN || (unsigned)d >= NN) return;
    int pos = g_rowptr[d] + atomicAdd(&g_cnt[d], 1);
    g_esrc[pos] = s;
}

// ---------------- GEMM + fused alpha projections ----------------------------
// h = act(X)@W written to g_h; as/ad = h·a_src / h·a_dst via 16-lane shuffles.
// Block: 256 threads, 64 rows/block; cx=tid&15 owns cols 4cx..4cx+3,
// ry=tid>>4 owns rows ry+16i (i=0..3). 4x4 register tile per thread.
template <int K, bool RELUIN, bool FROMAGG>
__global__ void gemm_kernel(const float* __restrict__ X, const float* __restrict__ W,
                            const float* __restrict__ avs, const float* __restrict__ avd) {
    __shared__ float sx[64][33];
    __shared__ float sw[32][64];
    int tid = threadIdx.x;
    int cx = tid & 15;
    int ry = tid >> 4;
    int row0 = blockIdx.x * 64;

    float acc[4][4];
#pragma unroll
    for (int i = 0; i < 4; i++)
#pragma unroll
        for (int j = 0; j < 4; j++) acc[i][j] = 0.f;

    for (int k0 = 0; k0 < K; k0 += 32) {
#pragma unroll
        for (int it = 0; it < 2; it++) {
            int i = tid + it * 256;
            int r = i >> 3;
            int c4 = i & 7;
            int gr = row0 + r;
            float4 v = make_float4(0.f, 0.f, 0.f, 0.f);
            if (gr < NN) {
                const float* src = FROMAGG ? (const float*)g_agg : X;
                v = *(const float4*)(src + (size_t)gr * K + k0 + c4 * 4);
            }
            if (RELUIN) {
                v.x = fmaxf(v.x, 0.f); v.y = fmaxf(v.y, 0.f);
                v.z = fmaxf(v.z, 0.f); v.w = fmaxf(v.w, 0.f);
            }
            sx[r][c4 * 4 + 0] = v.x;
            sx[r][c4 * 4 + 1] = v.y;
            sx[r][c4 * 4 + 2] = v.z;
            sx[r][c4 * 4 + 3] = v.w;
        }
#pragma unroll
        for (int it = 0; it < 2; it++) {
            int i = tid + it * 256;
            int r = i >> 4;
            int c4 = i & 15;
            *(float4*)&sw[r][c4 * 4] = *(const float4*)(W + (size_t)(r + k0) * 64 + c4 * 4);
        }
        __syncthreads();
#pragma unroll
        for (int kk = 0; kk < 32; kk++) {
            float4 wv = *(float4*)&sw[kk][cx * 4];
#pragma unroll
            for (int i = 0; i < 4; i++) {
                float xv = sx[ry + 16 * i][kk];
                acc[i][0] += xv * wv.x;
                acc[i][1] += xv * wv.y;
                acc[i][2] += xv * wv.z;
                acc[i][3] += xv * wv.w;
            }
        }
        __syncthreads();
    }

    float4 vs = *(const float4*)(avs + cx * 4);
    float4 vd = *(const float4*)(avd + cx * 4);

#pragma unroll
    for (int i = 0; i < 4; i++) {
        int gr = row0 + ry + 16 * i;
        if (gr < NN) {
            float4 v = make_float4(acc[i][0], acc[i][1], acc[i][2], acc[i][3]);
            *(float4*)(g_h + (size_t)gr * 64 + cx * 4) = v;
        }
        float ps = acc[i][0] * vs.x + acc[i][1] * vs.y + acc[i][2] * vs.z + acc[i][3] * vs.w;
        float pd = acc[i][0] * vd.x + acc[i][1] * vd.y + acc[i][2] * vd.z + acc[i][3] * vd.w;
#pragma unroll
        for (int o = 8; o; o >>= 1) {
            ps += __shfl_xor_sync(0xffffffffu, ps, o);
            pd += __shfl_xor_sync(0xffffffffu, pd, o);
        }
        if (cx == 0 && gr < NN) { g_as[gr] = ps; g_ad[gr] = pd; }
    }
}

// ---------------- edge aggregation: one warp per destination node -----------
// TOOUT=false -> write g_agg; TOOUT=true -> write out param.
template <bool TOOUT>
__global__ void edge_kernel(const float* __restrict__ bias, float* __restrict__ out) {
    int node = (blockIdx.x * blockDim.x + threadIdx.x) >> 5;
    int lane = threadIdx.x & 31;
    if (node >= NN) return;
    int beg = g_rowptr[node];
    int end = g_rowptr[node + 1];
    float addd = g_ad[node];

    // pass 1: segment max of leaky_relu(as[src] + ad[dst])
    float mx = -INFINITY;
    for (int j = beg + lane; j < end; j += 32) {
        float e = g_as[g_esrc[j]] + addd;
        e = (e > 0.f) ? e : NEG_SLOPE * e;
        mx = fmaxf(mx, e);
    }
#pragma unroll
    for (int o = 16; o; o >>= 1) mx = fmaxf(mx, __shfl_xor_sync(0xffffffffu, mx, o));

    // pass 2: sum of exp(e - max)
    float sum = 0.f;
    for (int j = beg + lane; j < end; j += 32) {
        float e = g_as[g_esrc[j]] + addd;
        e = (e > 0.f) ? e : NEG_SLOPE * e;
        sum += __expf(e - mx);
    }
#pragma unroll
    for (int o = 16; o; o >>= 1) sum += __shfl_xor_sync(0xffffffffu, sum, o);
    float inv = 1.f / (sum + 1e-16f);

    // pass 3: weighted gather-sum; lane owns channels 2*lane, 2*lane+1
    float a0 = 0.f, a1 = 0.f;
    for (int j0 = beg; j0 < end; j0 += 32) {
        int cnt = min(32, end - j0);
        int s = 0;
        float wgt = 0.f;
        if (lane < cnt) {
            s = g_esrc[j0 + lane];
            float e = g_as[s] + addd;
            e = (e > 0.f) ? e : NEG_SLOPE * e;
            wgt = __expf(e - mx) * inv;
        }
        for (int t = 0; t < cnt; t++) {
            int ss = __shfl_sync(0xffffffffu, s, t);
            float ww = __shfl_sync(0xffffffffu, wgt, t);
            float2 hv = *(const float2*)(g_h + (size_t)ss * 64 + 2 * lane);
            a0 += ww * hv.x;
            a1 += ww * hv.y;
        }
    }
    float o0 = a0 + bias[2 * lane + 0];
    float o1 = a1 + bias[2 * lane + 1];
    float* dst = TOOUT ? out : (float*)g_agg;
    dst[(size_t)node * 64 + 2 * lane + 0] = o0;
    dst[(size_t)node * 64 + 2 * lane + 1] = o1;
}

// ---------------- launch ----------------------------------------------------
extern "C" void kernel_launch(void* const* d_in, const int* in_sizes, int n_in,
                              void* d_out, int out_size) {
    const float* x    = (const float*)d_in[0];
    const int*   ei32 = (const int*)d_in[1];   // int32 OR int64 (probed on device)
    const float* W1   = (const float*)d_in[2];
    const float* a1s  = (const float*)d_in[3];
    const float* a1d  = (const float*)d_in[4];
    const float* b1   = (const float*)d_in[5];
    const float* W2   = (const float*)d_in[6];
    const float* a2s  = (const float*)d_in[7];
    const float* a2d  = (const float*)d_in[8];
    const float* b2   = (const float*)d_in[9];
    float*       out  = (float*)d_out;

    const int NB_N = (NN + 255) / 256;        // 391
    const int NB_E = (EE + 255) / 256;        // 3907
    const int NB_S = (NN + 1023) / 1024;      // 98
    const int NB_W = (NN * 32 + 255) / 256;   // 12500 (warp per node)
    const int NB_G = (NN + 63) / 64;          // 1563

    // --- CSR build (by destination) ---
    detect_kernel<<<1, 256>>>(ei32);
    zero_cnt_kernel<<<NB_N, 256>>>();
    hist_kernel<<<NB_E, 256>>>(ei32);
    scan1_kernel<<<NB_S, 1024>>>();
    scan2_kernel<<<1, 32>>>(NB_S);
    scan3_kernel<<<NB_N, 256>>>();
    zero_cnt_kernel<<<NB_N, 256>>>();
    scatter_kernel<<<NB_E, 256>>>(ei32);

    // --- layer 1 ---
    gemm_kernel<256, false, false><<<NB_G, 256>>>(x, W1, a1s, a1d);
    edge_kernel<false><<<NB_W, 256>>>(b1, nullptr);

    // --- layer 2 (relu on g_agg inside GEMM) ---
    gemm_kernel<64, true, true><<<NB_G, 256>>>(nullptr, W2, a2s, a2d);
    edge_kernel<true><<<NB_W, 256>>>(b2, out);
}

// round 10
// speedup vs baseline: 1.1090x; 1.1090x over previous
#include <cuda_runtime.h>
#include <cuda_bf16.h>
#include <math.h>

#define NN 100000
#define EE 1000000
#define NEG_SLOPE 0.2f

// ---------------- scratch (device globals) ----------------------------------
__device__ float g_h[(size_t)NN * 64];     // current layer feature h
__device__ float g_agg[(size_t)NN * 64];   // layer-1 aggregated output (+b1)
__device__ float g_as[NN];                 // alpha_src per node
__device__ float g_ad[NN];                 // alpha_dst per node
__device__ float g_w[EE];                  // per-edge logit -> weight cache
__device__ int   g_cnt[NN];                // histogram / scatter cursors
__device__ int   g_rowptr[NN + 1];         // CSR row pointers (by dst)
__device__ int   g_part[128];              // scan partials
__device__ int   g_esrc[EE];               // CSR: src node per edge slot
__device__ int   g_is64;                   // 1 if edge_index delivered as int64

// ---------------- dtype probe for edge_index --------------------------------
__global__ void detect_kernel(const int* __restrict__ ei32) {
    __shared__ int acc;
    int t = threadIdx.x;
    if (t == 0) acc = 0;
    __syncthreads();
    int v = 0;
    for (int i = t; i < 1024; i += 256) v |= ei32[2 * i + 1];
    if (v) atomicOr(&acc, 1);
    __syncthreads();
    if (t == 0) g_is64 = (acc == 0) ? 1 : 0;
}

__device__ __forceinline__ int edge_at(const int* ei32, long long idx) {
    if (g_is64) return (int)((const long long*)ei32)[idx];
    return ei32[idx];
}

// ---------------- CSR build kernels -----------------------------------------
__global__ void zero_cnt_kernel() {
    int i = blockIdx.x * blockDim.x + threadIdx.x;
    if (i < NN) g_cnt[i] = 0;
}

__global__ void scan1_kernel() {
    __shared__ int sm[1024];
    int t = threadIdx.x;
    int g = blockIdx.x * 1024 + t;
    int v = (g < NN) ? g_cnt[g] : 0;
    sm[t] = v;
    __syncthreads();
    for (int off = 1; off < 1024; off <<= 1) {
        int x = (t >= off) ? sm[t - off] : 0;
        __syncthreads();
        sm[t] += x;
        __syncthreads();
    }
    if (g < NN) g_rowptr[g] = sm[t] - v;   // exclusive
    if (t == 1023) g_part[blockIdx.x] = sm[t];
}

// parallel scan of the (<=128) block partials — replaces serial L2 pointer chase
__global__ void scan2_kernel(int nb) {
    __shared__ int sm[128];
    int t = threadIdx.x;
    int v = (t < nb) ? g_part[t] : 0;
    sm[t] = v;
    __syncthreads();
    for (int off = 1; off < 128; off <<= 1) {
        int x = (t >= off) ? sm[t - off] : 0;
        __syncthreads();
        sm[t] += x;
        __syncthreads();
    }
    if (t < nb) g_part[t] = sm[t] - v;     // exclusive
}

__global__ void scan3_kernel() {
    int g = blockIdx.x * blockDim.x + threadIdx.x;
    if (g < NN) g_rowptr[g] += g_part[g >> 10];
    if (g == 0) g_rowptr[NN] = EE;
}

__global__ void scatter_kernel(const int* __restrict__ ei32) {
    int i = blockIdx.x * blockDim.x + threadIdx.x;
    if (i >= EE) return;
    int s = edge_at(ei32, i);
    int d = edge_at(ei32, (long long)EE + i);
    if ((unsigned)s >= NN || (unsigned)d >= NN) return;
    int pos = g_rowptr[d] + atomicAdd(&g_cnt[d], 1);
    g_esrc[pos] = s;
}

// ---------------- GEMM body: 256 rows/block, 8x8 register tile --------------
// 256 threads: cx=tid&7 owns cols 8cx..8cx+7; ry=tid>>3 owns rows ry+32i, i=0..7.
// Writes g_h and fused alpha projections g_as/g_ad.
template <int K, bool RELUIN, bool FROMAGG>
__device__ __forceinline__ void gemm_block(
    int bx, const float* __restrict__ X, const float* __restrict__ W,
    const float* __restrict__ avs, const float* __restrict__ avd,
    float (*sx)[33], float (*sw)[64]) {
    int tid = threadIdx.x;
    int cx = tid & 7;
    int ry = tid >> 3;
    int row0 = bx * 256;

    float acc[8][8];
#pragma unroll
    for (int i = 0; i < 8; i++)
#pragma unroll
        for (int j = 0; j < 8; j++) acc[i][j] = 0.f;

    for (int k0 = 0; k0 < K; k0 += 32) {
        // X tile: 256 rows x 32 cols = 2048 float4, 8 per thread
#pragma unroll
        for (int it = 0; it < 8; it++) {
            int i = tid + it * 256;
            int r = i >> 3;
            int c4 = i & 7;
            int gr = row0 + r;
            float4 v = make_float4(0.f, 0.f, 0.f, 0.f);
            if (gr < NN) {
                const float* src = FROMAGG ? (const float*)g_agg : X;
                v = *(const float4*)(src + (size_t)gr * K + k0 + c4 * 4);
            }
            if (RELUIN) {
                v.x = fmaxf(v.x, 0.f); v.y = fmaxf(v.y, 0.f);
                v.z = fmaxf(v.z, 0.f); v.w = fmaxf(v.w, 0.f);
            }
            sx[r][c4 * 4 + 0] = v.x;
            sx[r][c4 * 4 + 1] = v.y;
            sx[r][c4 * 4 + 2] = v.z;
            sx[r][c4 * 4 + 3] = v.w;
        }
        // W tile: 32 x 64 = 512 float4, 2 per thread
#pragma unroll
        for (int it = 0; it < 2; it++) {
            int i = tid + it * 256;
            int r = i >> 4;
            int c4 = i & 15;
            *(float4*)&sw[r][c4 * 4] = *(const float4*)(W + (size_t)(r + k0) * 64 + c4 * 4);
        }
        __syncthreads();
#pragma unroll
        for (int kk = 0; kk < 32; kk++) {
            float4 w0 = *(float4*)&sw[kk][cx * 8];
            float4 w1 = *(float4*)&sw[kk][cx * 8 + 4];
#pragma unroll
            for (int i = 0; i < 8; i++) {
                float xv = sx[ry + 32 * i][kk];
                acc[i][0] += xv * w0.x;
                acc[i][1] += xv * w0.y;
                acc[i][2] += xv * w0.z;
                acc[i][3] += xv * w0.w;
                acc[i][4] += xv * w1.x;
                acc[i][5] += xv * w1.y;
                acc[i][6] += xv * w1.z;
                acc[i][7] += xv * w1.w;
            }
        }
        __syncthreads();
    }

    float4 vs0 = *(const float4*)(avs + cx * 8);
    float4 vs1 = *(const float4*)(avs + cx * 8 + 4);
    float4 vd0 = *(const float4*)(avd + cx * 8);
    float4 vd1 = *(const float4*)(avd + cx * 8 + 4);

#pragma unroll
    for (int i = 0; i < 8; i++) {
        int gr = row0 + ry + 32 * i;
        if (gr < NN) {
            *(float4*)(g_h + (size_t)gr * 64 + cx * 8) =
                make_float4(acc[i][0], acc[i][1], acc[i][2], acc[i][3]);
            *(float4*)(g_h + (size_t)gr * 64 + cx * 8 + 4) =
                make_float4(acc[i][4], acc[i][5], acc[i][6], acc[i][7]);
        }
        float ps = acc[i][0] * vs0.x + acc[i][1] * vs0.y + acc[i][2] * vs0.z + acc[i][3] * vs0.w
                 + acc[i][4] * vs1.x + acc[i][5] * vs1.y + acc[i][6] * vs1.z + acc[i][7] * vs1.w;
        float pd = acc[i][0] * vd0.x + acc[i][1] * vd0.y + acc[i][2] * vd0.z + acc[i][3] * vd0.w
                 + acc[i][4] * vd1.x + acc[i][5] * vd1.y + acc[i][6] * vd1.z + acc[i][7] * vd1.w;
        // reduce over the 8 cx lanes (lane bits 0..2)
#pragma unroll
        for (int o = 1; o < 8; o <<= 1) {
            ps += __shfl_xor_sync(0xffffffffu, ps, o);
            pd += __shfl_xor_sync(0xffffffffu, pd, o);
        }
        if (cx == 0 && gr < NN) { g_as[gr] = ps; g_ad[gr] = pd; }
    }
}

// layer-1 GEMM fused with the edge histogram (independent work, free overlap)
__global__ void __launch_bounds__(256, 2) gemm1_hist_kernel(
    const float* __restrict__ X, const float* __restrict__ W,
    const float* __restrict__ avs, const float* __restrict__ avd,
    const int* __restrict__ ei32, int nbg) {
    __shared__ float sx[256][33];
    __shared__ float sw[32][64];
    if (blockIdx.x < (unsigned)nbg) {
        gemm_block<256, false, false>(blockIdx.x, X, W, avs, avd, sx, sw);
    } else {
        int i = (blockIdx.x - nbg) * 256 + threadIdx.x;
        if (i < EE) {
            int d = edge_at(ei32, (long long)EE + i);
            if ((unsigned)d < NN) atomicAdd(&g_cnt[d], 1);
        }
    }
}

__global__ void __launch_bounds__(256, 2) gemm2_kernel(
    const float* __restrict__ W,
    const float* __restrict__ avs, const float* __restrict__ avd) {
    __shared__ float sx[256][33];
    __shared__ float sw[32][64];
    gemm_block<64, true, true>(blockIdx.x, nullptr, W, avs, avd, sx, sw);
}

// ---------------- edge aggregation: one warp per destination node -----------
template <bool TOOUT>
__global__ void edge_kernel(const float* __restrict__ bias, float* __restrict__ out) {
    int node = (blockIdx.x * blockDim.x + threadIdx.x) >> 5;
    int lane = threadIdx.x & 31;
    if (node >= NN) return;
    int beg = g_rowptr[node];
    int end = g_rowptr[node + 1];
    float addd = g_ad[node];

    // pass 1: gather logits once, cache, reduce max
    float mx = -INFINITY;
    for (int j = beg + lane; j < end; j += 32) {
        float e = g_as[g_esrc[j]] + addd;
        e = (e > 0.f) ? e : NEG_SLOPE * e;
        g_w[j] = e;
        mx = fmaxf(mx, e);
    }
#pragma unroll
    for (int o = 16; o; o >>= 1) mx = fmaxf(mx, __shfl_xor_sync(0xffffffffu, mx, o));

    // pass 2: exp + sum (sequential reads of cached logits)
    float sum = 0.f;
    for (int j = beg + lane; j < end; j += 32) {
        float w = __expf(g_w[j] - mx);
        g_w[j] = w;
        sum += w;
    }
#pragma unroll
    for (int o = 16; o; o >>= 1) sum += __shfl_xor_sync(0xffffffffu, sum, o);
    float inv = 1.f / (sum + 1e-16f);

    // pass 3: weighted gather-sum; lane owns channels 2*lane, 2*lane+1
    float a0 = 0.f, a1 = 0.f;
    for (int j0 = beg; j0 < end; j0 += 32) {
        int cnt = min(32, end - j0);
        int s = 0;
        float wgt = 0.f;
        if (lane < cnt) {
            s = g_esrc[j0 + lane];
            wgt = g_w[j0 + lane] * inv;
        }
        for (int t = 0; t < cnt; t++) {
            int ss = __shfl_sync(0xffffffffu, s, t);
            float ww = __shfl_sync(0xffffffffu, wgt, t);
            float2 hv = *(const float2*)(g_h + (size_t)ss * 64 + 2 * lane);
            a0 += ww * hv.x;
            a1 += ww * hv.y;
        }
    }
    float o0 = a0 + bias[2 * lane + 0];
    float o1 = a1 + bias[2 * lane + 1];
    float* dst = TOOUT ? out : (float*)g_agg;
    dst[(size_t)node * 64 + 2 * lane + 0] = o0;
    dst[(size_t)node * 64 + 2 * lane + 1] = o1;
}

// ---------------- launch ----------------------------------------------------
extern "C" void kernel_launch(void* const* d_in, const int* in_sizes, int n_in,
                              void* d_out, int out_size) {
    const float* x    = (const float*)d_in[0];
    const int*   ei32 = (const int*)d_in[1];   // int32 OR int64 (probed on device)
    const float* W1   = (const float*)d_in[2];
    const float* a1s  = (const float*)d_in[3];
    const float* a1d  = (const float*)d_in[4];
    const float* b1   = (const float*)d_in[5];
    const float* W2   = (const float*)d_in[6];
    const float* a2s  = (const float*)d_in[7];
    const float* a2d  = (const float*)d_in[8];
    const float* b2   = (const float*)d_in[9];
    float*       out  = (float*)d_out;

    const int NB_N = (NN + 255) / 256;        // 391
    const int NB_E = (EE + 255) / 256;        // 3907
    const int NB_S = (NN + 1023) / 1024;      // 98
    const int NB_W = (NN * 32 + 255) / 256;   // 12500 (warp per node)
    const int NB_G = (NN + 255) / 256;        // 391 (256-row gemm blocks)

    // --- dtype probe + zero counters ---
    detect_kernel<<<1, 256>>>(ei32);
    zero_cnt_kernel<<<NB_N, 256>>>();

    // --- layer-1 GEMM fused with histogram ---
    gemm1_hist_kernel<<<NB_G + NB_E, 256>>>(x, W1, a1s, a1d, ei32, NB_G);

    // --- CSR build ---
    scan1_kernel<<<NB_S, 1024>>>();
    scan2_kernel<<<1, 128>>>(NB_S);
    scan3_kernel<<<NB_N, 256>>>();
    zero_cnt_kernel<<<NB_N, 256>>>();
    scatter_kernel<<<NB_E, 256>>>(ei32);

    // --- layer 1 aggregate ---
    edge_kernel<false><<<NB_W, 256>>>(b1, nullptr);

    // --- layer 2 ---
    gemm2_kernel<<<NB_G, 256>>>(W2, a2s, a2d);
    edge_kernel<true><<<NB_W, 256>>>(b2, out);
}

// round 14
// speedup vs baseline: 1.3590x; 1.2254x over previous
#include <cuda_runtime.h>
#include <cuda_bf16.h>
#include <math.h>
#include <stdint.h>

#define NN 100000
#define EE 1000000
#define NEG_SLOPE 0.2f

// ---------------- scratch (device globals) ----------------------------------
__device__ float g_h[(size_t)NN * 64];
__device__ float g_agg[(size_t)NN * 64];
__device__ float g_as[NN];
__device__ float g_ad[NN];
__device__ float g_w[EE];
__device__ int   g_cnt[NN];
__device__ int   g_rowptr[NN + 1];
__device__ int   g_part[128];
__device__ int   g_esrc[EE];
__device__ int   g_is64;
// pre-converted weights, transposed to [n][k] bf16 hi/lo (k contiguous)
__device__ __nv_bfloat16 g_w1t_hi[64 * 256];
__device__ __nv_bfloat16 g_w1t_lo[64 * 256];
__device__ __nv_bfloat16 g_w2t_hi[64 * 64];
__device__ __nv_bfloat16 g_w2t_lo[64 * 64];

__device__ __forceinline__ unsigned short f2bf(float v) {
    return __bfloat16_as_ushort(__float2bfloat16(v));
}
__device__ __forceinline__ float bf2f(unsigned short u) {
    return __bfloat162float(__ushort_as_bfloat16(u));
}

// ---------------- dtype probe for edge_index --------------------------------
__global__ void detect_kernel(const int* __restrict__ ei32) {
    __shared__ int acc;
    int t = threadIdx.x;
    if (t == 0) acc = 0;
    __syncthreads();
    int v = 0;
    for (int i = t; i < 1024; i += 256) v |= ei32[2 * i + 1];
    if (v) atomicOr(&acc, 1);
    __syncthreads();
    if (t == 0) g_is64 = (acc == 0) ? 1 : 0;
}

__device__ __forceinline__ int edge_at(const int* ei32, long long idx) {
    if (g_is64) return (int)((const long long*)ei32)[idx];
    return ei32[idx];
}

// ---------------- CSR build kernels -----------------------------------------
__global__ void zero_cnt_kernel() {
    int i = blockIdx.x * blockDim.x + threadIdx.x;
    if (i < NN) g_cnt[i] = 0;
}

__global__ void hist_kernel(const int* __restrict__ ei32) {
    int i = blockIdx.x * blockDim.x + threadIdx.x;
    if (i >= EE) return;
    int d = edge_at(ei32, (long long)EE + i);
    if ((unsigned)d < NN) atomicAdd(&g_cnt[d], 1);
}

__global__ void scan1_kernel() {
    __shared__ int sm[1024];
    int t = threadIdx.x;
    int g = blockIdx.x * 1024 + t;
    int v = (g < NN) ? g_cnt[g] : 0;
    sm[t] = v;
    __syncthreads();
    for (int off = 1; off < 1024; off <<= 1) {
        int x = (t >= off) ? sm[t - off] : 0;
        __syncthreads();
        sm[t] += x;
        __syncthreads();
    }
    if (g < NN) g_rowptr[g] = sm[t] - v;
    if (t == 1023) g_part[blockIdx.x] = sm[t];
}

__global__ void scan2_kernel(int nb) {
    __shared__ int sm[128];
    int t = threadIdx.x;
    int v = (t < nb) ? g_part[t] : 0;
    sm[t] = v;
    __syncthreads();
    for (int off = 1; off < 128; off <<= 1) {
        int x = (t >= off) ? sm[t - off] : 0;
        __syncthreads();
        sm[t] += x;
        __syncthreads();
    }
    if (t < nb) g_part[t] = sm[t] - v;
}

__global__ void scan3_kernel() {
    int g = blockIdx.x * blockDim.x + threadIdx.x;
    if (g < NN) g_rowptr[g] += g_part[g >> 10];
    if (g == 0) g_rowptr[NN] = EE;
}

__global__ void scatter_kernel(const int* __restrict__ ei32) {
    int i = blockIdx.x * blockDim.x + threadIdx.x;
    if (i >= EE) return;
    int s = edge_at(ei32, i);
    int d = edge_at(ei32, (long long)EE + i);
    if ((unsigned)s >= NN || (unsigned)d >= NN) return;
    int pos = g_rowptr[d] + atomicAdd(&g_cnt[d], 1);
    g_esrc[pos] = s;
}

// ---------------- weight convert: W[K][64] fp32 -> Wt[n][k] bf16 hi/lo ------
__global__ void wconv_kernel(const float* __restrict__ W1, const float* __restrict__ W2) {
    int idx = blockIdx.x * blockDim.x + threadIdx.x;
    if (idx < 256 * 64) {
        int k = idx >> 6, n = idx & 63;
        float v = W1[idx];
        unsigned short h = f2bf(v);
        g_w1t_hi[n * 256 + k] = __ushort_as_bfloat16(h);
        g_w1t_lo[n * 256 + k] = __float2bfloat16(v - bf2f(h));
    } else if (idx < 256 * 64 + 64 * 64) {
        int j = idx - 256 * 64;
        int k = j >> 6, n = j & 63;
        float v = W2[j];
        unsigned short h = f2bf(v);
        g_w2t_hi[n * 64 + k] = __ushort_as_bfloat16(h);
        g_w2t_lo[n * 64 + k] = __float2bfloat16(v - bf2f(h));
    }
}

// ---------------- HMMA mma.sync split-bf16 GEMM -----------------------------
// D[128,64] per CTA = A[128,K] @ Wt^T, 3-term split bf16, fp32 accum.
// 8 warps; warp w owns rows w*16..w*16+15, all 8 n-tiles (m16n8k16 frags).
#define MMA_BF16(c, a0, a1, a2, a3, b0, b1) \
    asm volatile("mma.sync.aligned.m16n8k16.row.col.f32.bf16.bf16.f32 " \
        "{%0,%1,%2,%3}, {%4,%5,%6,%7}, {%8,%9}, {%0,%1,%2,%3};" \
        : "+f"((c)[0]), "+f"((c)[1]), "+f"((c)[2]), "+f"((c)[3]) \
        : "r"(a0), "r"(a1), "r"(a2), "r"(a3), "r"(b0), "r"(b1))

template <int KTOT, bool RELUIN, bool FROMAGG, bool L2W>
__global__ void __launch_bounds__(256) hmma_gemm_kernel(
    const float* __restrict__ X,
    const float* __restrict__ avs, const float* __restrict__ avd) {
    // stride 40 bf16 (80 B): frag LDS banks (20r + c/2) mod 32 conflict-free
    __shared__ __nv_bfloat16 sAh[128][40];
    __shared__ __nv_bfloat16 sAl[128][40];
    __shared__ __nv_bfloat16 sBh[64][40];
    __shared__ __nv_bfloat16 sBl[64][40];

    int tid = threadIdx.x, wid = tid >> 5, lane = tid & 31;
    int gid = lane >> 2, tin = lane & 3;
    int row0 = blockIdx.x * 128;

    float c[8][4];
#pragma unroll
    for (int i = 0; i < 8; i++)
#pragma unroll
        for (int j = 0; j < 4; j++) c[i][j] = 0.f;

    const __nv_bfloat16* Wh = L2W ? g_w2t_hi : g_w1t_hi;
    const __nv_bfloat16* Wl = L2W ? g_w2t_lo : g_w1t_lo;

    for (int ch = 0; ch < KTOT / 32; ch++) {
        // B copy: [64][32] bf16 hi+lo; thread -> n=tid>>2, k8=tid&3
        {
            int n = tid >> 2, k8 = tid & 3;
            *(uint4*)&sBh[n][k8 * 8] = *(const uint4*)(Wh + (size_t)n * KTOT + ch * 32 + k8 * 8);
            *(uint4*)&sBl[n][k8 * 8] = *(const uint4*)(Wl + (size_t)n * KTOT + ch * 32 + k8 * 8);
        }
        // A load+convert: thread -> row=tid>>1, half=tid&1 (16 floats)
        {
            int r = tid >> 1, hf = tid & 1;
            int gr = row0 + r;
            float4 v[4];
            if (gr < NN) {
                const float* rowp = (FROMAGG ? (const float*)g_agg : X)
                                    + (size_t)gr * KTOT + ch * 32 + hf * 16;
#pragma unroll
                for (int i = 0; i < 4; i++) v[i] = ((const float4*)rowp)[i];
            } else {
#pragma unroll
                for (int i = 0; i < 4; i++) v[i] = make_float4(0.f, 0.f, 0.f, 0.f);
            }
            if (RELUIN) {
#pragma unroll
                for (int i = 0; i < 4; i++) {
                    v[i].x = fmaxf(v[i].x, 0.f); v[i].y = fmaxf(v[i].y, 0.f);
                    v[i].z = fmaxf(v[i].z, 0.f); v[i].w = fmaxf(v[i].w, 0.f);
                }
            }
            uint32_t hi[8], lo[8];
#pragma unroll
            for (int i = 0; i < 4; i++) {
                unsigned short h0 = f2bf(v[i].x), h1 = f2bf(v[i].y);
                unsigned short h2 = f2bf(v[i].z), h3 = f2bf(v[i].w);
                hi[i * 2 + 0] = ((uint32_t)h1 << 16) | h0;
                hi[i * 2 + 1] = ((uint32_t)h3 << 16) | h2;
                unsigned short l0 = f2bf(v[i].x - bf2f(h0)), l1 = f2bf(v[i].y - bf2f(h1));
                unsigned short l2 = f2bf(v[i].z - bf2f(h2)), l3 = f2bf(v[i].w - bf2f(h3));
                lo[i * 2 + 0] = ((uint32_t)l1 << 16) | l0;
                lo[i * 2 + 1] = ((uint32_t)l3 << 16) | l2;
            }
            uint4* dh = (uint4*)&sAh[r][hf * 16];
            uint4* dl = (uint4*)&sAl[r][hf * 16];
            dh[0] = make_uint4(hi[0], hi[1], hi[2], hi[3]);
            dh[1] = make_uint4(hi[4], hi[5], hi[6], hi[7]);
            dl[0] = make_uint4(lo[0], lo[1], lo[2], lo[3]);
            dl[1] = make_uint4(lo[4], lo[5], lo[6], lo[7]);
        }
        __syncthreads();

#pragma unroll
        for (int ks = 0; ks < 2; ks++) {
            int kb = ks * 16;
            int ar = wid * 16 + gid;
            uint32_t ah0 = *(uint32_t*)&sAh[ar][kb + tin * 2];
            uint32_t ah1 = *(uint32_t*)&sAh[ar + 8][kb + tin * 2];
            uint32_t ah2 = *(uint32_t*)&sAh[ar][kb + tin * 2 + 8];
            uint32_t ah3 = *(uint32_t*)&sAh[ar + 8][kb + tin * 2 + 8];
            uint32_t al0 = *(uint32_t*)&sAl[ar][kb + tin * 2];
            uint32_t al1 = *(uint32_t*)&sAl[ar + 8][kb + tin * 2];
            uint32_t al2 = *(uint32_t*)&sAl[ar][kb + tin * 2 + 8];
            uint32_t al3 = *(uint32_t*)&sAl[ar + 8][kb + tin * 2 + 8];
#pragma unroll
            for (int nt = 0; nt < 8; nt++) {
                int br = nt * 8 + gid;
                uint32_t bh0 = *(uint32_t*)&sBh[br][kb + tin * 2];
                uint32_t bh1 = *(uint32_t*)&sBh[br][kb + tin * 2 + 8];
                uint32_t bl0 = *(uint32_t*)&sBl[br][kb + tin * 2];
                uint32_t bl1 = *(uint32_t*)&sBl[br][kb + tin * 2 + 8];
                MMA_BF16(c[nt], ah0, ah1, ah2, ah3, bh0, bh1);
                MMA_BF16(c[nt], ah0, ah1, ah2, ah3, bl0, bl1);
                MMA_BF16(c[nt], al0, al1, al2, al3, bh0, bh1);
            }
        }
        __syncthreads();
    }

    // epilogue: rows r0 = row0 + wid*16 + gid, r1 = r0 + 8
    int r0 = row0 + wid * 16 + gid;
    int r1 = r0 + 8;
    float ps0 = 0.f, pd0 = 0.f, ps1 = 0.f, pd1 = 0.f;
#pragma unroll
    for (int nt = 0; nt < 8; nt++) {
        int col = nt * 8 + tin * 2;
        float2 av = *(const float2*)(avs + col);
        float2 ad = *(const float2*)(avd + col);
        if (r0 < NN) *(float2*)(g_h + (size_t)r0 * 64 + col) = make_float2(c[nt][0], c[nt][1]);
        if (r1 < NN) *(float2*)(g_h + (size_t)r1 * 64 + col) = make_float2(c[nt][2], c[nt][3]);
        ps0 += c[nt][0] * av.x + c[nt][1] * av.y;
        pd0 += c[nt][0] * ad.x + c[nt][1] * ad.y;
        ps1 += c[nt][2] * av.x + c[nt][3] * av.y;
        pd1 += c[nt][2] * ad.x + c[nt][3] * ad.y;
    }
#pragma unroll
    for (int o = 1; o < 4; o <<= 1) {
        ps0 += __shfl_xor_sync(0xffffffffu, ps0, o);
        pd0 += __shfl_xor_sync(0xffffffffu, pd0, o);
        ps1 += __shfl_xor_sync(0xffffffffu, ps1, o);
        pd1 += __shfl_xor_sync(0xffffffffu, pd1, o);
    }
    if (tin == 0) {
        if (r0 < NN) { g_as[r0] = ps0; g_ad[r0] = pd0; }
        if (r1 < NN) { g_as[r1] = ps1; g_ad[r1] = pd1; }
    }
}

// ---------------- edge aggregation: one warp per destination node -----------
template <bool TOOUT>
__global__ void edge_kernel(const float* __restrict__ bias, float* __restrict__ out) {
    int node = (blockIdx.x * blockDim.x + threadIdx.x) >> 5;
    int lane = threadIdx.x & 31;
    if (node >= NN) return;
    int beg = g_rowptr[node];
    int end = g_rowptr[node + 1];
    float addd = g_ad[node];

    float mx = -INFINITY;
    for (int j = beg + lane; j < end; j += 32) {
        float e = g_as[g_esrc[j]] + addd;
        e = (e > 0.f) ? e : NEG_SLOPE * e;
        g_w[j] = e;
        mx = fmaxf(mx, e);
    }
#pragma unroll
    for (int o = 16; o; o >>= 1) mx = fmaxf(mx, __shfl_xor_sync(0xffffffffu, mx, o));

    float sum = 0.f;
    for (int j = beg + lane; j < end; j += 32) {
        float w = __expf(g_w[j] - mx);
        g_w[j] = w;
        sum += w;
    }
#pragma unroll
    for (int o = 16; o; o >>= 1) sum += __shfl_xor_sync(0xffffffffu, sum, o);
    float inv = 1.f / (sum + 1e-16f);

    float a0 = 0.f, a1 = 0.f;
    for (int j0 = beg; j0 < end; j0 += 32) {
        int cnt = min(32, end - j0);
        int s = 0;
        float wgt = 0.f;
        if (lane < cnt) {
            s = g_esrc[j0 + lane];
            wgt = g_w[j0 + lane] * inv;
        }
        for (int t = 0; t < cnt; t++) {
            int ss = __shfl_sync(0xffffffffu, s, t);
            float ww = __shfl_sync(0xffffffffu, wgt, t);
            float2 hv = *(const float2*)(g_h + (size_t)ss * 64 + 2 * lane);
            a0 += ww * hv.x;
            a1 += ww * hv.y;
        }
    }
    float o0 = a0 + bias[2 * lane + 0];
    float o1 = a1 + bias[2 * lane + 1];
    float* dst = TOOUT ? out : (float*)g_agg;
    dst[(size_t)node * 64 + 2 * lane + 0] = o0;
    dst[(size_t)node * 64 + 2 * lane + 1] = o1;
}

// ---------------- launch ----------------------------------------------------
extern "C" void kernel_launch(void* const* d_in, const int* in_sizes, int n_in,
                              void* d_out, int out_size) {
    const float* x    = (const float*)d_in[0];
    const int*   ei32 = (const int*)d_in[1];
    const float* W1   = (const float*)d_in[2];
    const float* a1s  = (const float*)d_in[3];
    const float* a1d  = (const float*)d_in[4];
    const float* b1   = (const float*)d_in[5];
    const float* W2   = (const float*)d_in[6];
    const float* a2s  = (const float*)d_in[7];
    const float* a2d  = (const float*)d_in[8];
    const float* b2   = (const float*)d_in[9];
    float*       out  = (float*)d_out;

    const int NB_N = (NN + 255) / 256;
    const int NB_E = (EE + 255) / 256;
    const int NB_S = (NN + 1023) / 1024;
    const int NB_W = (NN * 32 + 255) / 256;
    const int NB_M = (NN + 127) / 128;   // 782 GEMM CTAs

    // --- probe, weight convert, histogram ---
    detect_kernel<<<1, 256>>>(ei32);
    zero_cnt_kernel<<<NB_N, 256>>>();
    wconv_kernel<<<80, 256>>>(W1, W2);
    hist_kernel<<<NB_E, 256>>>(ei32);

    // --- layer-1 GEMM (mma.sync bf16 3-term) ---
    hmma_gemm_kernel<256, false, false, false><<<NB_M, 256>>>(x, a1s, a1d);

    // --- CSR build ---
    scan1_kernel<<<NB_S, 1024>>>();
    scan2_kernel<<<1, 128>>>(NB_S);
    scan3_kernel<<<NB_N, 256>>>();
    zero_cnt_kernel<<<NB_N, 256>>>();
    scatter_kernel<<<NB_E, 256>>>(ei32);

    // --- layer 1 aggregate ---
    edge_kernel<false><<<NB_W, 256>>>(b1, nullptr);

    // --- layer 2 ---
    hmma_gemm_kernel<64, true, true, true><<<NB_M, 256>>>(nullptr, a2s, a2d);
    edge_kernel<true><<<NB_W, 256>>>(b2, out);
}

// round 15
// speedup vs baseline: 1.5084x; 1.1100x over previous
#include <cuda_runtime.h>
#include <cuda_bf16.h>
#include <math.h>
#include <stdint.h>

#define NN 100000
#define EE 1000000
#define NEG_SLOPE 0.2f

// ---------------- scratch (device globals) ----------------------------------
__device__ float g_h[(size_t)NN * 64];
__device__ float g_agg[(size_t)NN * 64];
__device__ float g_as[NN];
__device__ float g_ad[NN];
__device__ float g_w[EE];
__device__ int   g_cnt[NN];
__device__ int   g_rowptr[NN + 1];
__device__ int   g_part[128];
__device__ int   g_esrc[EE];
__device__ int   g_is64;
// pre-converted weights, transposed to [n][k] bf16 hi/lo (k contiguous)
__device__ __nv_bfloat16 g_w1t_hi[64 * 256];
__device__ __nv_bfloat16 g_w1t_lo[64 * 256];
__device__ __nv_bfloat16 g_w2t_hi[64 * 64];
__device__ __nv_bfloat16 g_w2t_lo[64 * 64];

__device__ __forceinline__ unsigned short f2bf(float v) {
    return __bfloat16_as_ushort(__float2bfloat16(v));
}
__device__ __forceinline__ float bf2f(unsigned short u) {
    return __bfloat162float(__ushort_as_bfloat16(u));
}

// ---------------- streams/events for fork-join overlap (static init) --------
struct StreamsHolder {
    cudaStream_t s2;
    cudaEvent_t evA, evB;
    bool ok;
    StreamsHolder() : s2(0), evA(0), evB(0), ok(false) {
        if (cudaStreamCreateWithFlags(&s2, cudaStreamNonBlocking) == cudaSuccess &&
            cudaEventCreateWithFlags(&evA, cudaEventDisableTiming) == cudaSuccess &&
            cudaEventCreateWithFlags(&evB, cudaEventDisableTiming) == cudaSuccess)
            ok = true;
    }
};
static StreamsHolder g_str;

// ---------------- dtype probe for edge_index --------------------------------
__global__ void detect_kernel(const int* __restrict__ ei32) {
    __shared__ int acc;
    int t = threadIdx.x;
    if (t == 0) acc = 0;
    __syncthreads();
    int v = 0;
    for (int i = t; i < 1024; i += 256) v |= ei32[2 * i + 1];
    if (v) atomicOr(&acc, 1);
    __syncthreads();
    if (t == 0) g_is64 = (acc == 0) ? 1 : 0;
}

// ---------------- CSR build kernels -----------------------------------------
__global__ void zero_cnt_kernel() {
    int i = blockIdx.x * blockDim.x + threadIdx.x;
    if (i < NN) g_cnt[i] = 0;
}

// 2 edges per thread, vectorized index loads
__global__ void hist_kernel(const int* __restrict__ ei32) {
    int i = blockIdx.x * blockDim.x + threadIdx.x;   // pair index
    if (i >= EE / 2) return;
    int d0, d1;
    if (g_is64) {
        longlong2 v = ((const longlong2*)((const long long*)ei32 + EE))[i];
        d0 = (int)v.x; d1 = (int)v.y;
    } else {
        int2 v = ((const int2*)(ei32 + EE))[i];
        d0 = v.x; d1 = v.y;
    }
    if ((unsigned)d0 < NN) atomicAdd(&g_cnt[d0], 1);
    if ((unsigned)d1 < NN) atomicAdd(&g_cnt[d1], 1);
}

__global__ void scan1_kernel() {
    __shared__ int sm[1024];
    int t = threadIdx.x;
    int g = blockIdx.x * 1024 + t;
    int v = (g < NN) ? g_cnt[g] : 0;
    sm[t] = v;
    __syncthreads();
    for (int off = 1; off < 1024; off <<= 1) {
        int x = (t >= off) ? sm[t - off] : 0;
        __syncthreads();
        sm[t] += x;
        __syncthreads();
    }
    if (g < NN) g_rowptr[g] = sm[t] - v;
    if (t == 1023) g_part[blockIdx.x] = sm[t];
}

__global__ void scan2_kernel(int nb) {
    __shared__ int sm[128];
    int t = threadIdx.x;
    int v = (t < nb) ? g_part[t] : 0;
    sm[t] = v;
    __syncthreads();
    for (int off = 1; off < 128; off <<= 1) {
        int x = (t >= off) ? sm[t - off] : 0;
        __syncthreads();
        sm[t] += x;
        __syncthreads();
    }
    if (t < nb) g_part[t] = sm[t] - v;
}

__global__ void scan3_kernel() {
    int g = blockIdx.x * blockDim.x + threadIdx.x;
    if (g < NN) g_rowptr[g] += g_part[g >> 10];
    if (g == 0) g_rowptr[NN] = EE;
}

// 2 edges per thread, vectorized index loads
__global__ void scatter_kernel(const int* __restrict__ ei32) {
    int i = blockIdx.x * blockDim.x + threadIdx.x;   // pair index
    if (i >= EE / 2) return;
    int s0, s1, d0, d1;
    if (g_is64) {
        longlong2 S = ((const longlong2*)(const long long*)ei32)[i];
        longlong2 D = ((const longlong2*)((const long long*)ei32 + EE))[i];
        s0 = (int)S.x; s1 = (int)S.y; d0 = (int)D.x; d1 = (int)D.y;
    } else {
        int2 S = ((const int2*)ei32)[i];
        int2 D = ((const int2*)(ei32 + EE))[i];
        s0 = S.x; s1 = S.y; d0 = D.x; d1 = D.y;
    }
    if ((unsigned)s0 < NN && (unsigned)d0 < NN) {
        int pos = g_rowptr[d0] + atomicAdd(&g_cnt[d0], 1);
        g_esrc[pos] = s0;
    }
    if ((unsigned)s1 < NN && (unsigned)d1 < NN) {
        int pos = g_rowptr[d1] + atomicAdd(&g_cnt[d1], 1);
        g_esrc[pos] = s1;
    }
}

// ---------------- weight convert: W[K][64] fp32 -> Wt[n][k] bf16 hi/lo ------
__global__ void wconv_kernel(const float* __restrict__ W1, const float* __restrict__ W2) {
    int idx = blockIdx.x * blockDim.x + threadIdx.x;
    if (idx < 256 * 64) {
        int k = idx >> 6, n = idx & 63;
        float v = W1[idx];
        unsigned short h = f2bf(v);
        g_w1t_hi[n * 256 + k] = __ushort_as_bfloat16(h);
        g_w1t_lo[n * 256 + k] = __float2bfloat16(v - bf2f(h));
    } else if (idx < 256 * 64 + 64 * 64) {
        int j = idx - 256 * 64;
        int k = j >> 6, n = j & 63;
        float v = W2[j];
        unsigned short h = f2bf(v);
        g_w2t_hi[n * 64 + k] = __ushort_as_bfloat16(h);
        g_w2t_lo[n * 64 + k] = __float2bfloat16(v - bf2f(h));
    }
}

// ---------------- HMMA mma.sync split-bf16 GEMM -----------------------------
#define MMA_BF16(c, a0, a1, a2, a3, b0, b1) \
    asm volatile("mma.sync.aligned.m16n8k16.row.col.f32.bf16.bf16.f32 " \
        "{%0,%1,%2,%3}, {%4,%5,%6,%7}, {%8,%9}, {%0,%1,%2,%3};" \
        : "+f"((c)[0]), "+f"((c)[1]), "+f"((c)[2]), "+f"((c)[3]) \
        : "r"(a0), "r"(a1), "r"(a2), "r"(a3), "r"(b0), "r"(b1))

template <int KTOT, bool RELUIN, bool FROMAGG, bool L2W>
__global__ void __launch_bounds__(256) hmma_gemm_kernel(
    const float* __restrict__ X,
    const float* __restrict__ avs, const float* __restrict__ avd) {
    __shared__ __nv_bfloat16 sAh[128][40];
    __shared__ __nv_bfloat16 sAl[128][40];
    __shared__ __nv_bfloat16 sBh[64][40];
    __shared__ __nv_bfloat16 sBl[64][40];

    int tid = threadIdx.x, wid = tid >> 5, lane = tid & 31;
    int gid = lane >> 2, tin = lane & 3;
    int row0 = blockIdx.x * 128;

    float c[8][4];
#pragma unroll
    for (int i = 0; i < 8; i++)
#pragma unroll
        for (int j = 0; j < 4; j++) c[i][j] = 0.f;

    const __nv_bfloat16* Wh = L2W ? g_w2t_hi : g_w1t_hi;
    const __nv_bfloat16* Wl = L2W ? g_w2t_lo : g_w1t_lo;

    for (int ch = 0; ch < KTOT / 32; ch++) {
        {
            int n = tid >> 2, k8 = tid & 3;
            *(uint4*)&sBh[n][k8 * 8] = *(const uint4*)(Wh + (size_t)n * KTOT + ch * 32 + k8 * 8);
            *(uint4*)&sBl[n][k8 * 8] = *(const uint4*)(Wl + (size_t)n * KTOT + ch * 32 + k8 * 8);
        }
        {
            int r = tid >> 1, hf = tid & 1;
            int gr = row0 + r;
            float4 v[4];
            if (gr < NN) {
                const float* rowp = (FROMAGG ? (const float*)g_agg : X)
                                    + (size_t)gr * KTOT + ch * 32 + hf * 16;
#pragma unroll
                for (int i = 0; i < 4; i++) v[i] = ((const float4*)rowp)[i];
            } else {
#pragma unroll
                for (int i = 0; i < 4; i++) v[i] = make_float4(0.f, 0.f, 0.f, 0.f);
            }
            if (RELUIN) {
#pragma unroll
                for (int i = 0; i < 4; i++) {
                    v[i].x = fmaxf(v[i].x, 0.f); v[i].y = fmaxf(v[i].y, 0.f);
                    v[i].z = fmaxf(v[i].z, 0.f); v[i].w = fmaxf(v[i].w, 0.f);
                }
            }
            uint32_t hi[8], lo[8];
#pragma unroll
            for (int i = 0; i < 4; i++) {
                unsigned short h0 = f2bf(v[i].x), h1 = f2bf(v[i].y);
                unsigned short h2 = f2bf(v[i].z), h3 = f2bf(v[i].w);
                hi[i * 2 + 0] = ((uint32_t)h1 << 16) | h0;
                hi[i * 2 + 1] = ((uint32_t)h3 << 16) | h2;
                unsigned short l0 = f2bf(v[i].x - bf2f(h0)), l1 = f2bf(v[i].y - bf2f(h1));
                unsigned short l2 = f2bf(v[i].z - bf2f(h2)), l3 = f2bf(v[i].w - bf2f(h3));
                lo[i * 2 + 0] = ((uint32_t)l1 << 16) | l0;
                lo[i * 2 + 1] = ((uint32_t)l3 << 16) | l2;
            }
            uint4* dh = (uint4*)&sAh[r][hf * 16];
            uint4* dl = (uint4*)&sAl[r][hf * 16];
            dh[0] = make_uint4(hi[0], hi[1], hi[2], hi[3]);
            dh[1] = make_uint4(hi[4], hi[5], hi[6], hi[7]);
            dl[0] = make_uint4(lo[0], lo[1], lo[2], lo[3]);
            dl[1] = make_uint4(lo[4], lo[5], lo[6], lo[7]);
        }
        __syncthreads();

#pragma unroll
        for (int ks = 0; ks < 2; ks++) {
            int kb = ks * 16;
            int ar = wid * 16 + gid;
            uint32_t ah0 = *(uint32_t*)&sAh[ar][kb + tin * 2];
            uint32_t ah1 = *(uint32_t*)&sAh[ar + 8][kb + tin * 2];
            uint32_t ah2 = *(uint32_t*)&sAh[ar][kb + tin * 2 + 8];
            uint32_t ah3 = *(uint32_t*)&sAh[ar + 8][kb + tin * 2 + 8];
            uint32_t al0 = *(uint32_t*)&sAl[ar][kb + tin * 2];
            uint32_t al1 = *(uint32_t*)&sAl[ar + 8][kb + tin * 2];
            uint32_t al2 = *(uint32_t*)&sAl[ar][kb + tin * 2 + 8];
            uint32_t al3 = *(uint32_t*)&sAl[ar + 8][kb + tin * 2 + 8];
#pragma unroll
            for (int nt = 0; nt < 8; nt++) {
                int br = nt * 8 + gid;
                uint32_t bh0 = *(uint32_t*)&sBh[br][kb + tin * 2];
                uint32_t bh1 = *(uint32_t*)&sBh[br][kb + tin * 2 + 8];
                uint32_t bl0 = *(uint32_t*)&sBl[br][kb + tin * 2];
                uint32_t bl1 = *(uint32_t*)&sBl[br][kb + tin * 2 + 8];
                MMA_BF16(c[nt], ah0, ah1, ah2, ah3, bh0, bh1);
                MMA_BF16(c[nt], ah0, ah1, ah2, ah3, bl0, bl1);
                MMA_BF16(c[nt], al0, al1, al2, al3, bh0, bh1);
            }
        }
        __syncthreads();
    }

    int r0 = row0 + wid * 16 + gid;
    int r1 = r0 + 8;
    float ps0 = 0.f, pd0 = 0.f, ps1 = 0.f, pd1 = 0.f;
#pragma unroll
    for (int nt = 0; nt < 8; nt++) {
        int col = nt * 8 + tin * 2;
        float2 av = *(const float2*)(avs + col);
        float2 ad = *(const float2*)(avd + col);
        if (r0 < NN) *(float2*)(g_h + (size_t)r0 * 64 + col) = make_float2(c[nt][0], c[nt][1]);
        if (r1 < NN) *(float2*)(g_h + (size_t)r1 * 64 + col) = make_float2(c[nt][2], c[nt][3]);
        ps0 += c[nt][0] * av.x + c[nt][1] * av.y;
        pd0 += c[nt][0] * ad.x + c[nt][1] * ad.y;
        ps1 += c[nt][2] * av.x + c[nt][3] * av.y;
        pd1 += c[nt][2] * ad.x + c[nt][3] * ad.y;
    }
#pragma unroll
    for (int o = 1; o < 4; o <<= 1) {
        ps0 += __shfl_xor_sync(0xffffffffu, ps0, o);
        pd0 += __shfl_xor_sync(0xffffffffu, pd0, o);
        ps1 += __shfl_xor_sync(0xffffffffu, ps1, o);
        pd1 += __shfl_xor_sync(0xffffffffu, pd1, o);
    }
    if (tin == 0) {
        if (r0 < NN) { g_as[r0] = ps0; g_ad[r0] = pd0; }
        if (r1 < NN) { g_as[r1] = ps1; g_ad[r1] = pd1; }
    }
}

// ---------------- edge aggregation: one warp per destination node -----------
// pass A: gather logits + online (max, scaled-sum); pass B: weighted gather
template <bool TOOUT>
__global__ void edge_kernel(const float* __restrict__ bias, float* __restrict__ out) {
    int node = (blockIdx.x * blockDim.x + threadIdx.x) >> 5;
    int lane = threadIdx.x & 31;
    if (node >= NN) return;
    int beg = g_rowptr[node];
    int end = g_rowptr[node + 1];
    float addd = g_ad[node];

    // online softmax accumulation per lane
    float m = -INFINITY, s = 0.f;
    for (int j = beg + lane; j < end; j += 32) {
        float e = g_as[g_esrc[j]] + addd;
        e = (e > 0.f) ? e : NEG_SLOPE * e;
        g_w[j] = e;
        if (e > m) { s = s * __expf(m - e) + 1.f; m = e; }
        else       { s += __expf(e - m); }
    }
    // warp combine (m, s) pairs; guard empty lanes (s==0)
#pragma unroll
    for (int o = 16; o; o >>= 1) {
        float mo = __shfl_xor_sync(0xffffffffu, m, o);
        float so = __shfl_xor_sync(0xffffffffu, s, o);
        float mn = fmaxf(m, mo);
        float t1 = (s  > 0.f) ? s  * __expf(m  - mn) : 0.f;
        float t2 = (so > 0.f) ? so * __expf(mo - mn) : 0.f;
        s = t1 + t2;
        m = mn;
    }
    float inv = 1.f / (s + 1e-16f);

    // weighted gather-sum; lane owns channels 2*lane, 2*lane+1
    float a0 = 0.f, a1 = 0.f;
    for (int j0 = beg; j0 < end; j0 += 32) {
        int cnt = min(32, end - j0);
        int src = 0;
        float wgt = 0.f;
        if (lane < cnt) {
            src = g_esrc[j0 + lane];
            wgt = __expf(g_w[j0 + lane] - m) * inv;
        }
        for (int t = 0; t < cnt; t++) {
            int ss = __shfl_sync(0xffffffffu, src, t);
            float ww = __shfl_sync(0xffffffffu, wgt, t);
            float2 hv = *(const float2*)(g_h + (size_t)ss * 64 + 2 * lane);
            a0 += ww * hv.x;
            a1 += ww * hv.y;
        }
    }
    float o0 = a0 + bias[2 * lane + 0];
    float o1 = a1 + bias[2 * lane + 1];
    float* dst = TOOUT ? out : (float*)g_agg;
    dst[(size_t)node * 64 + 2 * lane + 0] = o0;
    dst[(size_t)node * 64 + 2 * lane + 1] = o1;
}

// ---------------- launch ----------------------------------------------------
extern "C" void kernel_launch(void* const* d_in, const int* in_sizes, int n_in,
                              void* d_out, int out_size) {
    const float* x    = (const float*)d_in[0];
    const int*   ei32 = (const int*)d_in[1];
    const float* W1   = (const float*)d_in[2];
    const float* a1s  = (const float*)d_in[3];
    const float* a1d  = (const float*)d_in[4];
    const float* b1   = (const float*)d_in[5];
    const float* W2   = (const float*)d_in[6];
    const float* a2s  = (const float*)d_in[7];
    const float* a2d  = (const float*)d_in[8];
    const float* b2   = (const float*)d_in[9];
    float*       out  = (float*)d_out;

    const int NB_N  = (NN + 255) / 256;
    const int NB_E2 = (EE / 2 + 255) / 256;   // 1954 (2 edges/thread)
    const int NB_S  = (NN + 1023) / 1024;
    const int NB_W  = (NN * 32 + 255) / 256;
    const int NB_M  = (NN + 127) / 128;

    cudaStream_t sB = g_str.ok ? g_str.s2 : (cudaStream_t)0;

    // --- common prologue on stream 0 ---
    detect_kernel<<<1, 256>>>(ei32);
    zero_cnt_kernel<<<NB_N, 256>>>();

    if (g_str.ok) {
        cudaEventRecord(g_str.evA, 0);
        cudaStreamWaitEvent(sB, g_str.evA, 0);
    }

    // --- branch B: CSR build ---
    hist_kernel<<<NB_E2, 256, 0, sB>>>(ei32);
    scan1_kernel<<<NB_S, 1024, 0, sB>>>();
    scan2_kernel<<<1, 128, 0, sB>>>(NB_S);
    scan3_kernel<<<NB_N, 256, 0, sB>>>();
    zero_cnt_kernel<<<NB_N, 256, 0, sB>>>();
    scatter_kernel<<<NB_E2, 256, 0, sB>>>(ei32);
    if (g_str.ok) cudaEventRecord(g_str.evB, sB);

    // --- branch A: weight convert + layer-1 GEMM (stream 0) ---
    wconv_kernel<<<80, 256>>>(W1, W2);
    hmma_gemm_kernel<256, false, false, false><<<NB_M, 256>>>(x, a1s, a1d);

    if (g_str.ok) cudaStreamWaitEvent(0, g_str.evB, 0);

    // --- join: layer-1 aggregate, layer 2 ---
    edge_kernel<false><<<NB_W, 256>>>(b1, nullptr);
    hmma_gemm_kernel<64, true, true, true><<<NB_M, 256>>>(nullptr, a2s, a2d);
    edge_kernel<true><<<NB_W, 256>>>(b2, out);
}

// round 16
// speedup vs baseline: 1.6020x; 1.0621x over previous
#include <cuda_runtime.h>
#include <cuda_bf16.h>
#include <cuda_fp16.h>
#include <math.h>
#include <stdint.h>

#define NN 100000
#define EE 1000000
#define NEG_SLOPE 0.2f

// ---------------- scratch (device globals) ----------------------------------
__device__ __half g_hh[(size_t)NN * 64];   // h in fp16 (edge-gather payload)
__device__ float g_agg[(size_t)NN * 64];   // layer-1 aggregated output (fp32)
__device__ float g_as[NN];
__device__ float g_ad[NN];
__device__ float g_w[EE];                  // cached exp(logit) per edge slot
__device__ int   g_cnt[NN];
__device__ int   g_rowptr[NN + 1];
__device__ int   g_part[128];
__device__ int   g_esrc[EE];
__device__ int   g_is64;
// pre-converted weights, transposed to [n][k] bf16 hi/lo (k contiguous)
__device__ __nv_bfloat16 g_w1t_hi[64 * 256];
__device__ __nv_bfloat16 g_w1t_lo[64 * 256];
__device__ __nv_bfloat16 g_w2t_hi[64 * 64];
__device__ __nv_bfloat16 g_w2t_lo[64 * 64];

__device__ __forceinline__ unsigned short f2bf(float v) {
    return __bfloat16_as_ushort(__float2bfloat16(v));
}
__device__ __forceinline__ float bf2f(unsigned short u) {
    return __bfloat162float(__ushort_as_bfloat16(u));
}

// ---------------- streams/events for fork-join overlap (static init) --------
struct StreamsHolder {
    cudaStream_t s2;
    cudaEvent_t evA, evB;
    bool ok;
    StreamsHolder() : s2(0), evA(0), evB(0), ok(false) {
        if (cudaStreamCreateWithFlags(&s2, cudaStreamNonBlocking) == cudaSuccess &&
            cudaEventCreateWithFlags(&evA, cudaEventDisableTiming) == cudaSuccess &&
            cudaEventCreateWithFlags(&evB, cudaEventDisableTiming) == cudaSuccess)
            ok = true;
    }
};
static StreamsHolder g_str;

// ---------------- dtype probe for edge_index --------------------------------
__global__ void detect_kernel(const int* __restrict__ ei32) {
    __shared__ int acc;
    int t = threadIdx.x;
    if (t == 0) acc = 0;
    __syncthreads();
    int v = 0;
    for (int i = t; i < 1024; i += 256) v |= ei32[2 * i + 1];
    if (v) atomicOr(&acc, 1);
    __syncthreads();
    if (t == 0) g_is64 = (acc == 0) ? 1 : 0;
}

// ---------------- CSR build kernels -----------------------------------------
__global__ void zero_cnt_kernel() {
    int i = blockIdx.x * blockDim.x + threadIdx.x;
    if (i < NN) g_cnt[i] = 0;
}

__global__ void hist_kernel(const int* __restrict__ ei32) {
    int i = blockIdx.x * blockDim.x + threadIdx.x;   // pair index
    if (i >= EE / 2) return;
    int d0, d1;
    if (g_is64) {
        longlong2 v = ((const longlong2*)((const long long*)ei32 + EE))[i];
        d0 = (int)v.x; d1 = (int)v.y;
    } else {
        int2 v = ((const int2*)(ei32 + EE))[i];
        d0 = v.x; d1 = v.y;
    }
    if ((unsigned)d0 < NN) atomicAdd(&g_cnt[d0], 1);
    if ((unsigned)d1 < NN) atomicAdd(&g_cnt[d1], 1);
}

__global__ void scan1_kernel() {
    __shared__ int sm[1024];
    int t = threadIdx.x;
    int g = blockIdx.x * 1024 + t;
    int v = (g < NN) ? g_cnt[g] : 0;
    sm[t] = v;
    __syncthreads();
    for (int off = 1; off < 1024; off <<= 1) {
        int x = (t >= off) ? sm[t - off] : 0;
        __syncthreads();
        sm[t] += x;
        __syncthreads();
    }
    if (g < NN) g_rowptr[g] = sm[t] - v;
    if (t == 1023) g_part[blockIdx.x] = sm[t];
}

__global__ void scan2_kernel(int nb) {
    __shared__ int sm[128];
    int t = threadIdx.x;
    int v = (t < nb) ? g_part[t] : 0;
    sm[t] = v;
    __syncthreads();
    for (int off = 1; off < 128; off <<= 1) {
        int x = (t >= off) ? sm[t - off] : 0;
        __syncthreads();
        sm[t] += x;
        __syncthreads();
    }
    if (t < nb) g_part[t] = sm[t] - v;
}

__global__ void scan3_kernel() {
    int g = blockIdx.x * blockDim.x + threadIdx.x;
    if (g < NN) g_rowptr[g] += g_part[g >> 10];
    if (g == 0) g_rowptr[NN] = EE;
}

__global__ void scatter_kernel(const int* __restrict__ ei32) {
    int i = blockIdx.x * blockDim.x + threadIdx.x;   // pair index
    if (i >= EE / 2) return;
    int s0, s1, d0, d1;
    if (g_is64) {
        longlong2 S = ((const longlong2*)(const long long*)ei32)[i];
        longlong2 D = ((const longlong2*)((const long long*)ei32 + EE))[i];
        s0 = (int)S.x; s1 = (int)S.y; d0 = (int)D.x; d1 = (int)D.y;
    } else {
        int2 S = ((const int2*)ei32)[i];
        int2 D = ((const int2*)(ei32 + EE))[i];
        s0 = S.x; s1 = S.y; d0 = D.x; d1 = D.y;
    }
    if ((unsigned)s0 < NN && (unsigned)d0 < NN) {
        int pos = g_rowptr[d0] + atomicAdd(&g_cnt[d0], 1);
        g_esrc[pos] = s0;
    }
    if ((unsigned)s1 < NN && (unsigned)d1 < NN) {
        int pos = g_rowptr[d1] + atomicAdd(&g_cnt[d1], 1);
        g_esrc[pos] = s1;
    }
}

// ---------------- weight convert: W[K][64] fp32 -> Wt[n][k] bf16 hi/lo ------
__global__ void wconv_kernel(const float* __restrict__ W1, const float* __restrict__ W2) {
    int idx = blockIdx.x * blockDim.x + threadIdx.x;
    if (idx < 256 * 64) {
        int k = idx >> 6, n = idx & 63;
        float v = W1[idx];
        unsigned short h = f2bf(v);
        g_w1t_hi[n * 256 + k] = __ushort_as_bfloat16(h);
        g_w1t_lo[n * 256 + k] = __float2bfloat16(v - bf2f(h));
    } else if (idx < 256 * 64 + 64 * 64) {
        int j = idx - 256 * 64;
        int k = j >> 6, n = j & 63;
        float v = W2[j];
        unsigned short h = f2bf(v);
        g_w2t_hi[n * 64 + k] = __ushort_as_bfloat16(h);
        g_w2t_lo[n * 64 + k] = __float2bfloat16(v - bf2f(h));
    }
}

// ---------------- HMMA mma.sync split-bf16 GEMM -----------------------------
#define MMA_BF16(c, a0, a1, a2, a3, b0, b1) \
    asm volatile("mma.sync.aligned.m16n8k16.row.col.f32.bf16.bf16.f32 " \
        "{%0,%1,%2,%3}, {%4,%5,%6,%7}, {%8,%9}, {%0,%1,%2,%3};" \
        : "+f"((c)[0]), "+f"((c)[1]), "+f"((c)[2]), "+f"((c)[3]) \
        : "r"(a0), "r"(a1), "r"(a2), "r"(a3), "r"(b0), "r"(b1))

template <int KTOT, bool RELUIN, bool FROMAGG, bool L2W>
__global__ void __launch_bounds__(256) hmma_gemm_kernel(
    const float* __restrict__ X,
    const float* __restrict__ avs, const float* __restrict__ avd) {
    __shared__ __nv_bfloat16 sAh[128][40];
    __shared__ __nv_bfloat16 sAl[128][40];
    __shared__ __nv_bfloat16 sBh[64][40];
    __shared__ __nv_bfloat16 sBl[64][40];

    int tid = threadIdx.x, wid = tid >> 5, lane = tid & 31;
    int gid = lane >> 2, tin = lane & 3;
    int row0 = blockIdx.x * 128;

    float c[8][4];
#pragma unroll
    for (int i = 0; i < 8; i++)
#pragma unroll
        for (int j = 0; j < 4; j++) c[i][j] = 0.f;

    const __nv_bfloat16* Wh = L2W ? g_w2t_hi : g_w1t_hi;
    const __nv_bfloat16* Wl = L2W ? g_w2t_lo : g_w1t_lo;

    for (int ch = 0; ch < KTOT / 32; ch++) {
        {
            int n = tid >> 2, k8 = tid & 3;
            *(uint4*)&sBh[n][k8 * 8] = *(const uint4*)(Wh + (size_t)n * KTOT + ch * 32 + k8 * 8);
            *(uint4*)&sBl[n][k8 * 8] = *(const uint4*)(Wl + (size_t)n * KTOT + ch * 32 + k8 * 8);
        }
        {
            int r = tid >> 1, hf = tid & 1;
            int gr = row0 + r;
            float4 v[4];
            if (gr < NN) {
                const float* rowp = (FROMAGG ? (const float*)g_agg : X)
                                    + (size_t)gr * KTOT + ch * 32 + hf * 16;
#pragma unroll
                for (int i = 0; i < 4; i++) v[i] = ((const float4*)rowp)[i];
            } else {
#pragma unroll
                for (int i = 0; i < 4; i++) v[i] = make_float4(0.f, 0.f, 0.f, 0.f);
            }
            if (RELUIN) {
#pragma unroll
                for (int i = 0; i < 4; i++) {
                    v[i].x = fmaxf(v[i].x, 0.f); v[i].y = fmaxf(v[i].y, 0.f);
                    v[i].z = fmaxf(v[i].z, 0.f); v[i].w = fmaxf(v[i].w, 0.f);
                }
            }
            uint32_t hi[8], lo[8];
#pragma unroll
            for (int i = 0; i < 4; i++) {
                unsigned short h0 = f2bf(v[i].x), h1 = f2bf(v[i].y);
                unsigned short h2 = f2bf(v[i].z), h3 = f2bf(v[i].w);
                hi[i * 2 + 0] = ((uint32_t)h1 << 16) | h0;
                hi[i * 2 + 1] = ((uint32_t)h3 << 16) | h2;
                unsigned short l0 = f2bf(v[i].x - bf2f(h0)), l1 = f2bf(v[i].y - bf2f(h1));
                unsigned short l2 = f2bf(v[i].z - bf2f(h2)), l3 = f2bf(v[i].w - bf2f(h3));
                lo[i * 2 + 0] = ((uint32_t)l1 << 16) | l0;
                lo[i * 2 + 1] = ((uint32_t)l3 << 16) | l2;
            }
            uint4* dh = (uint4*)&sAh[r][hf * 16];
            uint4* dl = (uint4*)&sAl[r][hf * 16];
            dh[0] = make_uint4(hi[0], hi[1], hi[2], hi[3]);
            dh[1] = make_uint4(hi[4], hi[5], hi[6], hi[7]);
            dl[0] = make_uint4(lo[0], lo[1], lo[2], lo[3]);
            dl[1] = make_uint4(lo[4], lo[5], lo[6], lo[7]);
        }
        __syncthreads();

#pragma unroll
        for (int ks = 0; ks < 2; ks++) {
            int kb = ks * 16;
            int ar = wid * 16 + gid;
            uint32_t ah0 = *(uint32_t*)&sAh[ar][kb + tin * 2];
            uint32_t ah1 = *(uint32_t*)&sAh[ar + 8][kb + tin * 2];
            uint32_t ah2 = *(uint32_t*)&sAh[ar][kb + tin * 2 + 8];
            uint32_t ah3 = *(uint32_t*)&sAh[ar + 8][kb + tin * 2 + 8];
            uint32_t al0 = *(uint32_t*)&sAl[ar][kb + tin * 2];
            uint32_t al1 = *(uint32_t*)&sAl[ar + 8][kb + tin * 2];
            uint32_t al2 = *(uint32_t*)&sAl[ar][kb + tin * 2 + 8];
            uint32_t al3 = *(uint32_t*)&sAl[ar + 8][kb + tin * 2 + 8];
#pragma unroll
            for (int nt = 0; nt < 8; nt++) {
                int br = nt * 8 + gid;
                uint32_t bh0 = *(uint32_t*)&sBh[br][kb + tin * 2];
                uint32_t bh1 = *(uint32_t*)&sBh[br][kb + tin * 2 + 8];
                uint32_t bl0 = *(uint32_t*)&sBl[br][kb + tin * 2];
                uint32_t bl1 = *(uint32_t*)&sBl[br][kb + tin * 2 + 8];
                MMA_BF16(c[nt], ah0, ah1, ah2, ah3, bh0, bh1);
                MMA_BF16(c[nt], ah0, ah1, ah2, ah3, bl0, bl1);
                MMA_BF16(c[nt], al0, al1, al2, al3, bh0, bh1);
            }
        }
        __syncthreads();
    }

    int r0 = row0 + wid * 16 + gid;
    int r1 = r0 + 8;
    float ps0 = 0.f, pd0 = 0.f, ps1 = 0.f, pd1 = 0.f;
#pragma unroll
    for (int nt = 0; nt < 8; nt++) {
        int col = nt * 8 + tin * 2;
        float2 av = *(const float2*)(avs + col);
        float2 ad = *(const float2*)(avd + col);
        if (r0 < NN) *(__half2*)(g_hh + (size_t)r0 * 64 + col) = __floats2half2_rn(c[nt][0], c[nt][1]);
        if (r1 < NN) *(__half2*)(g_hh + (size_t)r1 * 64 + col) = __floats2half2_rn(c[nt][2], c[nt][3]);
        ps0 += c[nt][0] * av.x + c[nt][1] * av.y;
        pd0 += c[nt][0] * ad.x + c[nt][1] * ad.y;
        ps1 += c[nt][2] * av.x + c[nt][3] * av.y;
        pd1 += c[nt][2] * ad.x + c[nt][3] * ad.y;
    }
#pragma unroll
    for (int o = 1; o < 4; o <<= 1) {
        ps0 += __shfl_xor_sync(0xffffffffu, ps0, o);
        pd0 += __shfl_xor_sync(0xffffffffu, pd0, o);
        ps1 += __shfl_xor_sync(0xffffffffu, ps1, o);
        pd1 += __shfl_xor_sync(0xffffffffu, pd1, o);
    }
    if (tin == 0) {
        if (r0 < NN) { g_as[r0] = ps0; g_ad[r0] = pd0; }
        if (r1 < NN) { g_as[r1] = ps1; g_ad[r1] = pd1; }
    }
}

// ---------------- edge aggregation: one warp per destination node -----------
// softmax without max-shift (logits bounded): pass A computes w=exp(e)+sum,
// pass B accumulates unnormalized and scales once by inv.
template <bool TOOUT>
__global__ void edge_kernel(const float* __restrict__ bias, float* __restrict__ out) {
    int node = (blockIdx.x * blockDim.x + threadIdx.x) >> 5;
    int lane = threadIdx.x & 31;
    if (node >= NN) return;
    int beg = g_rowptr[node];
    int end = g_rowptr[node + 1];
    float addd = g_ad[node];

    // pass A: single gather, exp, sum
    float s = 0.f;
    for (int j = beg + lane; j < end; j += 32) {
        float e = g_as[g_esrc[j]] + addd;
        e = (e > 0.f) ? e : NEG_SLOPE * e;
        float w = __expf(e);
        g_w[j] = w;
        s += w;
    }
#pragma unroll
    for (int o = 16; o; o >>= 1) s += __shfl_xor_sync(0xffffffffu, s, o);
    float inv = 1.f / (s + 1e-16f);

    // pass B: unnormalized weighted gather-sum (fp16 h payload)
    float a0 = 0.f, a1 = 0.f;
    for (int j0 = beg; j0 < end; j0 += 32) {
        int cnt = min(32, end - j0);
        int src = 0;
        float wgt = 0.f;
        if (lane < cnt) {
            src = g_esrc[j0 + lane];
            wgt = g_w[j0 + lane];
        }
        for (int t = 0; t < cnt; t++) {
            int ss = __shfl_sync(0xffffffffu, src, t);
            float ww = __shfl_sync(0xffffffffu, wgt, t);
            __half2 hv = *(const __half2*)(g_hh + (size_t)ss * 64 + 2 * lane);
            float2 f = __half22float2(hv);
            a0 += ww * f.x;
            a1 += ww * f.y;
        }
    }
    float o0 = a0 * inv + bias[2 * lane + 0];
    float o1 = a1 * inv + bias[2 * lane + 1];
    float* dst = TOOUT ? out : (float*)g_agg;
    dst[(size_t)node * 64 + 2 * lane + 0] = o0;
    dst[(size_t)node * 64 + 2 * lane + 1] = o1;
}

// ---------------- launch ----------------------------------------------------
extern "C" void kernel_launch(void* const* d_in, const int* in_sizes, int n_in,
                              void* d_out, int out_size) {
    const float* x    = (const float*)d_in[0];
    const int*   ei32 = (const int*)d_in[1];
    const float* W1   = (const float*)d_in[2];
    const float* a1s  = (const float*)d_in[3];
    const float* a1d  = (const float*)d_in[4];
    const float* b1   = (const float*)d_in[5];
    const float* W2   = (const float*)d_in[6];
    const float* a2s  = (const float*)d_in[7];
    const float* a2d  = (const float*)d_in[8];
    const float* b2   = (const float*)d_in[9];
    float*       out  = (float*)d_out;

    const int NB_N  = (NN + 255) / 256;
    const int NB_E2 = (EE / 2 + 255) / 256;
    const int NB_S  = (NN + 1023) / 1024;
    const int NB_W  = (NN * 32 + 255) / 256;
    const int NB_M  = (NN + 127) / 128;

    cudaStream_t sB = g_str.ok ? g_str.s2 : (cudaStream_t)0;

    // --- common prologue on stream 0 ---
    detect_kernel<<<1, 256>>>(ei32);
    zero_cnt_kernel<<<NB_N, 256>>>();

    if (g_str.ok) {
        cudaEventRecord(g_str.evA, 0);
        cudaStreamWaitEvent(sB, g_str.evA, 0);
    }

    // --- branch B: CSR build ---
    hist_kernel<<<NB_E2, 256, 0, sB>>>(ei32);
    scan1_kernel<<<NB_S, 1024, 0, sB>>>();
    scan2_kernel<<<1, 128, 0, sB>>>(NB_S);
    scan3_kernel<<<NB_N, 256, 0, sB>>>();
    zero_cnt_kernel<<<NB_N, 256, 0, sB>>>();
    scatter_kernel<<<NB_E2, 256, 0, sB>>>(ei32);
    if (g_str.ok) cudaEventRecord(g_str.evB, sB);

    // --- branch A: weight convert + layer-1 GEMM (stream 0) ---
    wconv_kernel<<<80, 256>>>(W1, W2);
    hmma_gemm_kernel<256, false, false, false><<<NB_M, 256>>>(x, a1s, a1d);

    if (g_str.ok) cudaStreamWaitEvent(0, g_str.evB, 0);

    // --- join: layer-1 aggregate, layer 2 ---
    edge_kernel<false><<<NB_W, 256>>>(b1, nullptr);
    hmma_gemm_kernel<64, true, true, true><<<NB_M, 256>>>(nullptr, a2s, a2d);
    edge_kernel<true><<<NB_W, 256>>>(b2, out);
}

// round 17
// speedup vs baseline: 1.6837x; 1.0510x over previous
#include <cuda_runtime.h>
#include <cuda_bf16.h>
#include <cuda_fp16.h>
#include <math.h>
#include <stdint.h>

#define NN 100000
#define EE 1000000
#define NEG_SLOPE 0.2f

// ---------------- scratch (device globals) ----------------------------------
__device__ __half g_hh[(size_t)NN * 64];   // h in fp16 (edge-gather payload)
__device__ float g_agg[(size_t)NN * 64];   // layer-1 aggregated output (fp32)
__device__ float g_as[NN];
__device__ float g_ad[NN];
__device__ int   g_cnt[NN];                // histogram, then scatter cursors
__device__ int   g_rowptr[NN + 1];
__device__ int   g_part[128];
__device__ int   g_esrc[EE];
__device__ int   g_is64;
// pre-converted weights, transposed to [n][k] bf16 hi/lo (k contiguous)
__device__ __nv_bfloat16 g_w1t_hi[64 * 256];
__device__ __nv_bfloat16 g_w1t_lo[64 * 256];
__device__ __nv_bfloat16 g_w2t_hi[64 * 64];
__device__ __nv_bfloat16 g_w2t_lo[64 * 64];

__device__ __forceinline__ unsigned short f2bf(float v) {
    return __bfloat16_as_ushort(__float2bfloat16(v));
}
__device__ __forceinline__ float bf2f(unsigned short u) {
    return __bfloat162float(__ushort_as_bfloat16(u));
}

// ---------------- streams/events for fork-join overlap (static init) --------
struct StreamsHolder {
    cudaStream_t s2;
    cudaEvent_t evA, evB;
    bool ok;
    StreamsHolder() : s2(0), evA(0), evB(0), ok(false) {
        if (cudaStreamCreateWithFlags(&s2, cudaStreamNonBlocking) == cudaSuccess &&
            cudaEventCreateWithFlags(&evA, cudaEventDisableTiming) == cudaSuccess &&
            cudaEventCreateWithFlags(&evB, cudaEventDisableTiming) == cudaSuccess)
            ok = true;
    }
};
static StreamsHolder g_str;

// ---------------- dtype probe for edge_index --------------------------------
__global__ void detect_kernel(const int* __restrict__ ei32) {
    __shared__ int acc;
    int t = threadIdx.x;
    if (t == 0) acc = 0;
    __syncthreads();
    int v = 0;
    for (int i = t; i < 1024; i += 256) v |= ei32[2 * i + 1];
    if (v) atomicOr(&acc, 1);
    __syncthreads();
    if (t == 0) g_is64 = (acc == 0) ? 1 : 0;
}

// ---------------- CSR build kernels -----------------------------------------
__global__ void zero_cnt_kernel() {
    int i = blockIdx.x * blockDim.x + threadIdx.x;
    if (i < NN) g_cnt[i] = 0;
}

__global__ void hist_kernel(const int* __restrict__ ei32) {
    int i = blockIdx.x * blockDim.x + threadIdx.x;   // pair index
    if (i >= EE / 2) return;
    int d0, d1;
    if (g_is64) {
        longlong2 v = ((const longlong2*)((const long long*)ei32 + EE))[i];
        d0 = (int)v.x; d1 = (int)v.y;
    } else {
        int2 v = ((const int2*)(ei32 + EE))[i];
        d0 = v.x; d1 = v.y;
    }
    if ((unsigned)d0 < NN) atomicAdd(&g_cnt[d0], 1);
    if ((unsigned)d1 < NN) atomicAdd(&g_cnt[d1], 1);
}

__global__ void scan1_kernel() {
    __shared__ int sm[1024];
    int t = threadIdx.x;
    int g = blockIdx.x * 1024 + t;
    int v = (g < NN) ? g_cnt[g] : 0;
    sm[t] = v;
    __syncthreads();
    for (int off = 1; off < 1024; off <<= 1) {
        int x = (t >= off) ? sm[t - off] : 0;
        __syncthreads();
        sm[t] += x;
        __syncthreads();
    }
    if (g < NN) g_rowptr[g] = sm[t] - v;
    if (t == 1023) g_part[blockIdx.x] = sm[t];
}

__global__ void scan2_kernel(int nb) {
    __shared__ int sm[128];
    int t = threadIdx.x;
    int v = (t < nb) ? g_part[t] : 0;
    sm[t] = v;
    __syncthreads();
    for (int off = 1; off < 128; off <<= 1) {
        int x = (t >= off) ? sm[t - off] : 0;
        __syncthreads();
        sm[t] += x;
        __syncthreads();
    }
    if (t < nb) g_part[t] = sm[t] - v;
}

// writes final exclusive prefix into BOTH rowptr and cnt (cnt = scatter cursor)
__global__ void scan3_kernel() {
    int g = blockIdx.x * blockDim.x + threadIdx.x;
    if (g < NN) {
        int v = g_rowptr[g] + g_part[g >> 10];
        g_rowptr[g] = v;
        g_cnt[g] = v;
    }
    if (g == 0) g_rowptr[NN] = EE;
}

// cursor-based scatter: single atomic returns slot (no rowptr gather)
__global__ void scatter_kernel(const int* __restrict__ ei32) {
    int i = blockIdx.x * blockDim.x + threadIdx.x;   // pair index
    if (i >= EE / 2) return;
    int s0, s1, d0, d1;
    if (g_is64) {
        longlong2 S = ((const longlong2*)(const long long*)ei32)[i];
        longlong2 D = ((const longlong2*)((const long long*)ei32 + EE))[i];
        s0 = (int)S.x; s1 = (int)S.y; d0 = (int)D.x; d1 = (int)D.y;
    } else {
        int2 S = ((const int2*)ei32)[i];
        int2 D = ((const int2*)(ei32 + EE))[i];
        s0 = S.x; s1 = S.y; d0 = D.x; d1 = D.y;
    }
    if ((unsigned)s0 < NN && (unsigned)d0 < NN)
        g_esrc[atomicAdd(&g_cnt[d0], 1)] = s0;
    if ((unsigned)s1 < NN && (unsigned)d1 < NN)
        g_esrc[atomicAdd(&g_cnt[d1], 1)] = s1;
}

// ---------------- weight convert: W[K][64] fp32 -> Wt[n][k] bf16 hi/lo ------
__global__ void wconv_kernel(const float* __restrict__ W1, const float* __restrict__ W2) {
    int idx = blockIdx.x * blockDim.x + threadIdx.x;
    if (idx < 256 * 64) {
        int k = idx >> 6, n = idx & 63;
        float v = W1[idx];
        unsigned short h = f2bf(v);
        g_w1t_hi[n * 256 + k] = __ushort_as_bfloat16(h);
        g_w1t_lo[n * 256 + k] = __float2bfloat16(v - bf2f(h));
    } else if (idx < 256 * 64 + 64 * 64) {
        int j = idx - 256 * 64;
        int k = j >> 6, n = j & 63;
        float v = W2[j];
        unsigned short h = f2bf(v);
        g_w2t_hi[n * 64 + k] = __ushort_as_bfloat16(h);
        g_w2t_lo[n * 64 + k] = __float2bfloat16(v - bf2f(h));
    }
}

// ---------------- HMMA mma.sync split-bf16 GEMM -----------------------------
#define MMA_BF16(c, a0, a1, a2, a3, b0, b1) \
    asm volatile("mma.sync.aligned.m16n8k16.row.col.f32.bf16.bf16.f32 " \
        "{%0,%1,%2,%3}, {%4,%5,%6,%7}, {%8,%9}, {%0,%1,%2,%3};" \
        : "+f"((c)[0]), "+f"((c)[1]), "+f"((c)[2]), "+f"((c)[3]) \
        : "r"(a0), "r"(a1), "r"(a2), "r"(a3), "r"(b0), "r"(b1))

template <int KTOT, bool RELUIN, bool FROMAGG, bool L2W>
__global__ void __launch_bounds__(256) hmma_gemm_kernel(
    const float* __restrict__ X,
    const float* __restrict__ avs, const float* __restrict__ avd) {
    __shared__ __nv_bfloat16 sAh[128][40];
    __shared__ __nv_bfloat16 sAl[128][40];
    __shared__ __nv_bfloat16 sBh[64][40];
    __shared__ __nv_bfloat16 sBl[64][40];

    int tid = threadIdx.x, wid = tid >> 5, lane = tid & 31;
    int gid = lane >> 2, tin = lane & 3;
    int row0 = blockIdx.x * 128;

    float c[8][4];
#pragma unroll
    for (int i = 0; i < 8; i++)
#pragma unroll
        for (int j = 0; j < 4; j++) c[i][j] = 0.f;

    const __nv_bfloat16* Wh = L2W ? g_w2t_hi : g_w1t_hi;
    const __nv_bfloat16* Wl = L2W ? g_w2t_lo : g_w1t_lo;

    for (int ch = 0; ch < KTOT / 32; ch++) {
        {
            int n = tid >> 2, k8 = tid & 3;
            *(uint4*)&sBh[n][k8 * 8] = *(const uint4*)(Wh + (size_t)n * KTOT + ch * 32 + k8 * 8);
            *(uint4*)&sBl[n][k8 * 8] = *(const uint4*)(Wl + (size_t)n * KTOT + ch * 32 + k8 * 8);
        }
        {
            int r = tid >> 1, hf = tid & 1;
            int gr = row0 + r;
            float4 v[4];
            if (gr < NN) {
                const float* rowp = (FROMAGG ? (const float*)g_agg : X)
                                    + (size_t)gr * KTOT + ch * 32 + hf * 16;
#pragma unroll
                for (int i = 0; i < 4; i++) v[i] = ((const float4*)rowp)[i];
            } else {
#pragma unroll
                for (int i = 0; i < 4; i++) v[i] = make_float4(0.f, 0.f, 0.f, 0.f);
            }
            if (RELUIN) {
#pragma unroll
                for (int i = 0; i < 4; i++) {
                    v[i].x = fmaxf(v[i].x, 0.f); v[i].y = fmaxf(v[i].y, 0.f);
                    v[i].z = fmaxf(v[i].z, 0.f); v[i].w = fmaxf(v[i].w, 0.f);
                }
            }
            uint32_t hi[8], lo[8];
#pragma unroll
            for (int i = 0; i < 4; i++) {
                unsigned short h0 = f2bf(v[i].x), h1 = f2bf(v[i].y);
                unsigned short h2 = f2bf(v[i].z), h3 = f2bf(v[i].w);
                hi[i * 2 + 0] = ((uint32_t)h1 << 16) | h0;
                hi[i * 2 + 1] = ((uint32_t)h3 << 16) | h2;
                unsigned short l0 = f2bf(v[i].x - bf2f(h0)), l1 = f2bf(v[i].y - bf2f(h1));
                unsigned short l2 = f2bf(v[i].z - bf2f(h2)), l3 = f2bf(v[i].w - bf2f(h3));
                lo[i * 2 + 0] = ((uint32_t)l1 << 16) | l0;
                lo[i * 2 + 1] = ((uint32_t)l3 << 16) | l2;
            }
            uint4* dh = (uint4*)&sAh[r][hf * 16];
            uint4* dl = (uint4*)&sAl[r][hf * 16];
            dh[0] = make_uint4(hi[0], hi[1], hi[2], hi[3]);
            dh[1] = make_uint4(hi[4], hi[5], hi[6], hi[7]);
            dl[0] = make_uint4(lo[0], lo[1], lo[2], lo[3]);
            dl[1] = make_uint4(lo[4], lo[5], lo[6], lo[7]);
        }
        __syncthreads();

#pragma unroll
        for (int ks = 0; ks < 2; ks++) {
            int kb = ks * 16;
            int ar = wid * 16 + gid;
            uint32_t ah0 = *(uint32_t*)&sAh[ar][kb + tin * 2];
            uint32_t ah1 = *(uint32_t*)&sAh[ar + 8][kb + tin * 2];
            uint32_t ah2 = *(uint32_t*)&sAh[ar][kb + tin * 2 + 8];
            uint32_t ah3 = *(uint32_t*)&sAh[ar + 8][kb + tin * 2 + 8];
            uint32_t al0 = *(uint32_t*)&sAl[ar][kb + tin * 2];
            uint32_t al1 = *(uint32_t*)&sAl[ar + 8][kb + tin * 2];
            uint32_t al2 = *(uint32_t*)&sAl[ar][kb + tin * 2 + 8];
            uint32_t al3 = *(uint32_t*)&sAl[ar + 8][kb + tin * 2 + 8];
#pragma unroll
            for (int nt = 0; nt < 8; nt++) {
                int br = nt * 8 + gid;
                uint32_t bh0 = *(uint32_t*)&sBh[br][kb + tin * 2];
                uint32_t bh1 = *(uint32_t*)&sBh[br][kb + tin * 2 + 8];
                uint32_t bl0 = *(uint32_t*)&sBl[br][kb + tin * 2];
                uint32_t bl1 = *(uint32_t*)&sBl[br][kb + tin * 2 + 8];
                MMA_BF16(c[nt], ah0, ah1, ah2, ah3, bh0, bh1);
                MMA_BF16(c[nt], ah0, ah1, ah2, ah3, bl0, bl1);
                MMA_BF16(c[nt], al0, al1, al2, al3, bh0, bh1);
            }
        }
        __syncthreads();
    }

    int r0 = row0 + wid * 16 + gid;
    int r1 = r0 + 8;
    float ps0 = 0.f, pd0 = 0.f, ps1 = 0.f, pd1 = 0.f;
#pragma unroll
    for (int nt = 0; nt < 8; nt++) {
        int col = nt * 8 + tin * 2;
        float2 av = *(const float2*)(avs + col);
        float2 ad = *(const float2*)(avd + col);
        if (r0 < NN) *(__half2*)(g_hh + (size_t)r0 * 64 + col) = __floats2half2_rn(c[nt][0], c[nt][1]);
        if (r1 < NN) *(__half2*)(g_hh + (size_t)r1 * 64 + col) = __floats2half2_rn(c[nt][2], c[nt][3]);
        ps0 += c[nt][0] * av.x + c[nt][1] * av.y;
        pd0 += c[nt][0] * ad.x + c[nt][1] * ad.y;
        ps1 += c[nt][2] * av.x + c[nt][3] * av.y;
        pd1 += c[nt][2] * ad.x + c[nt][3] * ad.y;
    }
#pragma unroll
    for (int o = 1; o < 4; o <<= 1) {
        ps0 += __shfl_xor_sync(0xffffffffu, ps0, o);
        pd0 += __shfl_xor_sync(0xffffffffu, pd0, o);
        ps1 += __shfl_xor_sync(0xffffffffu, ps1, o);
        pd1 += __shfl_xor_sync(0xffffffffu, pd1, o);
    }
    if (tin == 0) {
        if (r0 < NN) { g_as[r0] = ps0; g_ad[r0] = pd0; }
        if (r1 < NN) { g_as[r1] = ps1; g_ad[r1] = pd1; }
    }
}

// ---------------- edge aggregation: one warp per node, single pass ----------
// All lanes walk edges together: uniform loads of esrc/g_as (HW broadcast),
// redundant per-lane w=exp(leaky(e)) and running sum (identical across lanes),
// coalesced 128B h-row gather; normalize once at the end. No shuffles.
template <bool TOOUT>
__global__ void edge_kernel(const float* __restrict__ bias, float* __restrict__ out) {
    int node = (blockIdx.x * blockDim.x + threadIdx.x) >> 5;
    int lane = threadIdx.x & 31;
    if (node >= NN) return;
    int beg = g_rowptr[node];
    int end = g_rowptr[node + 1];
    float addd = g_ad[node];

    float ssum = 0.f, a0 = 0.f, a1 = 0.f;
#pragma unroll 4
    for (int j = beg; j < end; j++) {
        int s = g_esrc[j];                       // uniform
        float e = g_as[s] + addd;                // uniform random
        e = (e > 0.f) ? e : NEG_SLOPE * e;
        float w = __expf(e);
        ssum += w;
        __half2 hv = *(const __half2*)(g_hh + (size_t)s * 64 + 2 * lane);
        float2 f = __half22float2(hv);
        a0 += w * f.x;
        a1 += w * f.y;
    }
    float inv = 1.f / (ssum + 1e-16f);
    float o0 = a0 * inv + bias[2 * lane + 0];
    float o1 = a1 * inv + bias[2 * lane + 1];
    float* dst = TOOUT ? out : (float*)g_agg;
    dst[(size_t)node * 64 + 2 * lane + 0] = o0;
    dst[(size_t)node * 64 + 2 * lane + 1] = o1;
}

// ---------------- launch ----------------------------------------------------
extern "C" void kernel_launch(void* const* d_in, const int* in_sizes, int n_in,
                              void* d_out, int out_size) {
    const float* x    = (const float*)d_in[0];
    const int*   ei32 = (const int*)d_in[1];
    const float* W1   = (const float*)d_in[2];
    const float* a1s  = (const float*)d_in[3];
    const float* a1d  = (const float*)d_in[4];
    const float* b1   = (const float*)d_in[5];
    const float* W2   = (const float*)d_in[6];
    const float* a2s  = (const float*)d_in[7];
    const float* a2d  = (const float*)d_in[8];
    const float* b2   = (const float*)d_in[9];
    float*       out  = (float*)d_out;

    const int NB_N  = (NN + 255) / 256;
    const int NB_E2 = (EE / 2 + 255) / 256;
    const int NB_S  = (NN + 1023) / 1024;
    const int NB_W  = (NN * 32 + 255) / 256;
    const int NB_M  = (NN + 127) / 128;

    cudaStream_t sB = g_str.ok ? g_str.s2 : (cudaStream_t)0;

    // --- common prologue on stream 0 ---
    detect_kernel<<<1, 256>>>(ei32);
    zero_cnt_kernel<<<NB_N, 256>>>();

    if (g_str.ok) {
        cudaEventRecord(g_str.evA, 0);
        cudaStreamWaitEvent(sB, g_str.evA, 0);
    }

    // --- branch B: CSR build ---
    hist_kernel<<<NB_E2, 256, 0, sB>>>(ei32);
    scan1_kernel<<<NB_S, 1024, 0, sB>>>();
    scan2_kernel<<<1, 128, 0, sB>>>(NB_S);
    scan3_kernel<<<NB_N, 256, 0, sB>>>();   // rowptr + cursors
    scatter_kernel<<<NB_E2, 256, 0, sB>>>(ei32);
    if (g_str.ok) cudaEventRecord(g_str.evB, sB);

    // --- branch A: weight convert + layer-1 GEMM (stream 0) ---
    wconv_kernel<<<80, 256>>>(W1, W2);
    hmma_gemm_kernel<256, false, false, false><<<NB_M, 256>>>(x, a1s, a1d);

    if (g_str.ok) cudaStreamWaitEvent(0, g_str.evB, 0);

    // --- join: layer-1 aggregate, layer 2 ---
    edge_kernel<false><<<NB_W, 256>>>(b1, nullptr);
    hmma_gemm_kernel<64, true, true, true><<<NB_M, 256>>>(nullptr, a2s, a2d);
    edge_kernel<true><<<NB_W, 256>>>(b2, out);
}